// round 10
// baseline (speedup 1.0000x reference)
#include <cuda_runtime.h>
#include <cuda_bf16.h>
#include <math.h>
#include <stdint.h>

// Problem constants
#define NN   10000
#define NE   100000
#define HID  600
#define NGS  50
#define NITR 6

#define KP   640        // plane row stride (elements)
#define KC   608        // K compute extent (19 chunks of 32; cols 600..607 zero)
#define KP1  64         // padded gaussian K
#define NPAD 10112      // 79*128
#define GT   1024       // filter table resolution
#define DMAX 13.86f     // max possible distance: 8*sqrt(3)=13.8564
#define SMEM_BYTES (3 * 32768)

// ---------------------------------------------------------------------------
// Scratch (__device__ globals; zero-initialized at module load)
// ---------------------------------------------------------------------------
__device__ __align__(256) __nv_bfloat16 g_ea_h[(size_t)GT * KP1];
__device__ __align__(256) __nv_bfloat16 g_ea_l[(size_t)GT * KP1];
__device__ __align__(256) __nv_bfloat16 g_T1_h[(size_t)NITR * GT * KP];
__device__ __align__(256) __nv_bfloat16 g_T1_l[(size_t)NITR * GT * KP];
__device__ __align__(256) __nv_bfloat16 g_h_h [(size_t)NPAD * KP];
__device__ __align__(256) __nv_bfloat16 g_h_l [(size_t)NPAD * KP];
__device__ __align__(256) __nv_bfloat16 g_ag_h[(size_t)NPAD * KP];
__device__ __align__(256) __nv_bfloat16 g_ag_l[(size_t)NPAD * KP];
__device__ __align__(256) __nv_bfloat16 g_x2_h[(size_t)NPAD * KP];
__device__ __align__(256) __nv_bfloat16 g_x2_l[(size_t)NPAD * KP];
__device__ __align__(256) __nv_bfloat16 g_w1_h[(size_t)NITR * 640 * KP1];
__device__ __align__(256) __nv_bfloat16 g_w1_l[(size_t)NITR * 640 * KP1];
__device__ __align__(256) __nv_bfloat16 g_wb_h[(size_t)NITR * 4 * 640 * KP];
__device__ __align__(256) __nv_bfloat16 g_wb_l[(size_t)NITR * 4 * 640 * KP];
__device__ __align__(256) float g_tab [(size_t)NITR * GT * HID];  // filter tables
__device__ float g_x   [(size_t)NN * HID];
__device__ float g_Ct  [GT];        // cutoff on grid
__device__ int   g_ei0 [NE];        // per-edge table index
__device__ float g_efr [NE];        // per-edge interp fraction
// CSR (by target col)
__device__ int   g_cnt [NN];
__device__ int   g_off [NN + 1];
__device__ int   g_rank[NE];
__device__ int   g_csr [NE];

// ---------------------------------------------------------------------------
// Helpers
// ---------------------------------------------------------------------------
__device__ __forceinline__ uint32_t smem_u32(const void* p) {
    uint32_t a;
    asm("{ .reg .u64 t; cvta.to.shared.u64 t, %1; cvt.u32.u64 %0, t; }" : "=r"(a) : "l"(p));
    return a;
}
__device__ __forceinline__ void ldsm4(uint32_t (&r)[4], uint32_t addr) {
    asm volatile("ldmatrix.sync.aligned.m8n8.x4.shared.b16 {%0,%1,%2,%3}, [%4];"
                 : "=r"(r[0]), "=r"(r[1]), "=r"(r[2]), "=r"(r[3]) : "r"(addr));
}
__device__ __forceinline__ void mma16816(float (&d)[4], const uint32_t (&a)[4],
                                         uint32_t b0, uint32_t b1) {
    asm volatile("mma.sync.aligned.m16n8k16.row.col.f32.bf16.bf16.f32 "
                 "{%0,%1,%2,%3}, {%4,%5,%6,%7}, {%8,%9}, {%0,%1,%2,%3};"
                 : "+f"(d[0]), "+f"(d[1]), "+f"(d[2]), "+f"(d[3])
                 : "r"(a[0]), "r"(a[1]), "r"(a[2]), "r"(a[3]), "r"(b0), "r"(b1));
}
__device__ __forceinline__ void cpa16(uint32_t dst, const void* src) {
    asm volatile("cp.async.cg.shared.global [%0], [%1], 16;" :: "r"(dst), "l"(src));
}
__device__ __forceinline__ float ssp_f(float v) {
    float av = fabsf(v);
    return fmaxf(v, 0.0f) + log1pf(expf(-av)) - 0.69314718055994530942f;
}
__device__ __forceinline__ void split_bf(float v, unsigned short& h, unsigned short& l) {
    __nv_bfloat16 hi = __float2bfloat16(v);
    __nv_bfloat16 lo = __float2bfloat16(v - __bfloat162float(hi));
    h = __bfloat16_as_ushort(hi);
    l = __bfloat16_as_ushort(hi == hi ? __float2bfloat16(v - __bfloat162float(hi)) : hi);
    l = __bfloat16_as_ushort(__float2bfloat16(v - __bfloat162float(hi)));
}

// ---------------------------------------------------------------------------
// Fused prologue: block ranges do (a) table geometry, (b) edge prep, (c) h init
// g_cnt is zeroed by a memset launched before this kernel.
// ---------------------------------------------------------------------------
#define B_TAB  (GT / 256)                       // 4
#define B_EDGE ((NE + 255) / 256)               // 391
#define B_INIT ((NN * KP + 255) / 256)          // 25000

__global__ void prologue_kernel(const int* __restrict__ z, const float* __restrict__ emb,
                                const float* __restrict__ pos, const int* __restrict__ ei,
                                float* __restrict__ hout) {
    int bx = blockIdx.x;
    if (bx < B_TAB) {
        int g = bx * 256 + threadIdx.x;
        float d = (float)g * (DMAX / (float)(GT - 1));
        g_Ct[g] = 0.5f * (cosf(d * (float)(M_PI / 10.0)) + 1.0f);
        const float step  = 10.0f / 49.0f;
        const float coeff = -0.5f / (step * step);
        unsigned short* eh = (unsigned short*)g_ea_h + (size_t)g * KP1;
        unsigned short* el = (unsigned short*)g_ea_l + (size_t)g * KP1;
#pragma unroll 8
        for (int k = 0; k < KP1; k++) {
            float v = 0.0f;
            if (k < NGS) { float t = d - step * (float)k; v = expf(coeff * t * t); }
            unsigned short h, l; split_bf(v, h, l);
            eh[k] = h; el[k] = l;
        }
    } else if (bx < B_TAB + B_EDGE) {
        int e = (bx - B_TAB) * 256 + threadIdx.x;
        if (e >= NE) return;
        int r = ei[e], c = ei[NE + e];
        float dx = pos[3*r+0] - pos[3*c+0];
        float dy = pos[3*r+1] - pos[3*c+1];
        float dz = pos[3*r+2] - pos[3*c+2];
        float d = sqrtf(dx*dx + dy*dy + dz*dz);
        float t = d * ((float)(GT - 1) / DMAX);
        int i0 = (int)t;
        if (i0 > GT - 2) i0 = GT - 2;
        g_ei0[e] = i0;
        g_efr[e] = t - (float)i0;
        g_rank[e] = atomicAdd(&g_cnt[c], 1);
    } else {
        long i = (long)(bx - B_TAB - B_EDGE) * 256 + threadIdx.x;
        if (i >= (long)NN * KP) return;
        int n = (int)(i / KP), k = (int)(i - (long)n * KP);
        float v = (k < HID) ? emb[(size_t)z[n] * HID + k] : 0.0f;
        if (k < HID) hout[(size_t)n * HID + k] = v;
        unsigned short h, l; split_bf(v, h, l);
        ((unsigned short*)g_h_h)[i] = h;
        ((unsigned short*)g_h_l)[i] = l;
    }
}

// Exclusive scan of g_cnt -> g_off (single block, 1024 threads)
__global__ __launch_bounds__(1024)
void csr_scan_kernel() {
    __shared__ int part[1024];
    int t = threadIdx.x;
    int base = t * 10;
    int loc[10];
    int s = 0;
#pragma unroll
    for (int i = 0; i < 10; i++) {
        int idx = base + i;
        loc[i] = s;
        s += (idx < NN) ? g_cnt[idx] : 0;
    }
    part[t] = s;
    __syncthreads();
    for (int off = 1; off < 1024; off <<= 1) {
        int v = (t >= off) ? part[t - off] : 0;
        __syncthreads();
        if (t >= off) part[t] += v;
        __syncthreads();
    }
    int pre = (t > 0) ? part[t - 1] : 0;
#pragma unroll
    for (int i = 0; i < 10; i++) {
        int idx = base + i;
        if (idx < NN) g_off[idx] = pre + loc[i];
    }
    if (t == 1023) g_off[NN] = part[1023];
}

__global__ void csr_place_kernel(const int* __restrict__ ei) {
    int e = blockIdx.x * blockDim.x + threadIdx.x;
    if (e >= NE) return;
    int c = ei[NE + e];
    g_csr[g_off[c] + g_rank[e]] = e;
}

// Batched split of the 24 HID x HID weights (z = it*4 + wix)
__global__ void split_wb_kernel(const float* __restrict__ w2, const float* __restrict__ l1,
                                const float* __restrict__ l2, const float* __restrict__ lw) {
    int zz = blockIdx.z;
    int wix = zz & 3, it = zz >> 2;
    const float* src = ((wix == 0) ? w2 : (wix == 1) ? l1 : (wix == 2) ? l2 : lw)
                       + (size_t)it * HID * HID;
    unsigned short* dh = (unsigned short*)g_wb_h + (size_t)zz * 640 * KP;
    unsigned short* dl = (unsigned short*)g_wb_l + (size_t)zz * 640 * KP;
    long i = blockIdx.x * (long)blockDim.x + threadIdx.x;
    if (i >= (long)600 * KP) return;
    int r = (int)(i / KP), k = (int)(i - (long)r * KP);
    float v = (k < HID) ? src[(size_t)r * HID + k] : 0.0f;
    unsigned short h, l; split_bf(v, h, l);
    dh[i] = h; dl[i] = l;
}

// Batched split of the 6 mlp1 weights (z = it)
__global__ void split_w1_kernel(const float* __restrict__ w1) {
    int it = blockIdx.z;
    const float* src = w1 + (size_t)it * HID * NGS;
    unsigned short* dh = (unsigned short*)g_w1_h + (size_t)it * 640 * KP1;
    unsigned short* dl = (unsigned short*)g_w1_l + (size_t)it * 640 * KP1;
    long i = blockIdx.x * (long)blockDim.x + threadIdx.x;
    if (i >= (long)600 * KP1) return;
    int r = (int)(i / KP1), k = (int)(i - (long)r * KP1);
    float v = (k < NGS) ? src[(size_t)r * NGS + k] : 0.0f;
    unsigned short h, l; split_bf(v, h, l);
    dh[i] = h; dl[i] = l;
}

// ---------------------------------------------------------------------------
// bf16x3 HMMA GEMM, 128x128 tile, 2 CTAs/SM, 3-stage pipeline (R7 dual-sync)
// out[m,n] = sum_k A[m,k]*B[n,k];  Kc = compute extent, ldA = plane row stride
// OUTM: 0 = fp32 out; 1 = bf16 planes out; 2 = fp32 residual-add + planes out
// ---------------------------------------------------------------------------
template <int DO_BIAS, int DO_SSP, int DO_RSCALE, int OUTM>
__global__ __launch_bounds__(256, 2)
void hgemm(const __nv_bfloat16* __restrict__ Ah, const __nv_bfloat16* __restrict__ Al,
           const __nv_bfloat16* __restrict__ Bh, const __nv_bfloat16* __restrict__ Bl,
           const float* __restrict__ bias, const float* __restrict__ rowscale,
           float* __restrict__ Cf,
           __nv_bfloat16* __restrict__ Ph, __nv_bfloat16* __restrict__ Pl,
           int M, int Kc, int ldA,
           size_t aZ, size_t bZ, size_t biasZ, size_t cZ, size_t pZ) {
    extern __shared__ char smem[];
    const uint32_t sb = smem_u32(smem);
    const int tid = threadIdx.x, lane = tid & 31, wid = tid >> 5;
    const int wm = wid >> 2, wn = wid & 3;          // 2 x 4 warp grid, 64x32 warp tile
    const int m0 = blockIdx.y * 128, n0 = blockIdx.x * 128;
    const int zz = blockIdx.z;

    Ah += (size_t)zz * aZ;  Al += (size_t)zz * aZ;
    Bh += (size_t)zz * bZ;  Bl += (size_t)zz * bZ;
    if (DO_BIAS)   bias += (size_t)zz * biasZ;
    if (OUTM != 1) Cf   += (size_t)zz * cZ;
    if (OUTM >= 1) { Ph += (size_t)zz * pZ; Pl += (size_t)zz * pZ; }

    float acc[4][4][4];
#pragma unroll
    for (int a = 0; a < 4; a++)
#pragma unroll
        for (int b = 0; b < 4; b++)
#pragma unroll
            for (int c = 0; c < 4; c++) acc[a][b][c] = 0.0f;

    const __nv_bfloat16* srcs[4] = { Ah, Al, Bh, Bl };
    const int lr = tid >> 2;
    const int lc = tid & 3;

#define PREFETCH(chunk, stg) do {                                              \
        uint32_t sbase = sb + (stg) * 32768;                                   \
        int k0 = (chunk) * 32;                                                 \
        _Pragma("unroll")                                                      \
        for (int t = 0; t < 4; t++) {                                          \
            const __nv_bfloat16* s = srcs[t];                                  \
            int rb = (t < 2) ? m0 : n0;                                        \
            _Pragma("unroll")                                                  \
            for (int i = 0; i < 2; i++) {                                      \
                int r = i * 64 + lr;                                           \
                const void* g = s + (size_t)(rb + r) * ldA + k0 + lc * 8;      \
                uint32_t d = sbase + t * 8192 + r * 64 +                       \
                             ((lc ^ ((r >> 1) & 3)) * 16);                     \
                cpa16(d, g);                                                   \
            }                                                                  \
        }                                                                      \
        asm volatile("cp.async.commit_group;" ::: "memory");                   \
    } while (0)

    const int nc = Kc >> 5;
    PREFETCH(0, 0);
    if (nc > 1) PREFETCH(1, 1);
    for (int ch = 0; ch < nc; ch++) {
        int stg = ch % 3;
        if (ch + 1 < nc) {
            asm volatile("cp.async.wait_group 1;" ::: "memory");
        } else {
            asm volatile("cp.async.wait_group 0;" ::: "memory");
        }
        __syncthreads();
        if (ch + 2 < nc) PREFETCH(ch + 2, (ch + 2) % 3);

        uint32_t Abase = sb + stg * 32768;
        uint32_t Bbase = Abase + 16384;
#pragma unroll
        for (int ks = 0; ks < 2; ks++) {
            int arow = wm * 64 + (lane & 15);
            int brow = wn * 32 + (lane & 15);
            int cch  = ks * 2 + (lane >> 4);
            uint32_t af[4][4], bhf[2][4], blf[2][4];
#pragma unroll
            for (int p = 0; p < 2; p++) {
                int r = brow + p * 16;
                ldsm4(bhf[p], Bbase + r * 64 + ((cch ^ ((r >> 1) & 3)) * 16));
            }
#pragma unroll
            for (int p = 0; p < 2; p++) {
                int r = brow + p * 16;
                ldsm4(blf[p], Bbase + 8192 + r * 64 + ((cch ^ ((r >> 1) & 3)) * 16));
            }
            // A-hi pass: Ah*Bh and Ah*Bl
#pragma unroll
            for (int mi = 0; mi < 4; mi++) {
                int r = arow + mi * 16;
                ldsm4(af[mi], Abase + r * 64 + ((cch ^ ((r >> 1) & 3)) * 16));
            }
#pragma unroll
            for (int mi = 0; mi < 4; mi++)
#pragma unroll
                for (int ni = 0; ni < 4; ni++)
                    mma16816(acc[mi][ni], af[mi], bhf[ni >> 1][ni & 1], bhf[ni >> 1][(ni & 1) + 2]);
#pragma unroll
            for (int mi = 0; mi < 4; mi++)
#pragma unroll
                for (int ni = 0; ni < 4; ni++)
                    mma16816(acc[mi][ni], af[mi], blf[ni >> 1][ni & 1], blf[ni >> 1][(ni & 1) + 2]);
            // A-lo pass (reuse af): Al*Bh
#pragma unroll
            for (int mi = 0; mi < 4; mi++) {
                int r = arow + mi * 16;
                ldsm4(af[mi], Abase + 8192 + r * 64 + ((cch ^ ((r >> 1) & 3)) * 16));
            }
#pragma unroll
            for (int mi = 0; mi < 4; mi++)
#pragma unroll
                for (int ni = 0; ni < 4; ni++)
                    mma16816(acc[mi][ni], af[mi], bhf[ni >> 1][ni & 1], bhf[ni >> 1][(ni & 1) + 2]);
        }
        __syncthreads();   // R7 config: protect stage before it is refilled
    }
#undef PREFETCH

    const int gid = lane >> 2, tg = lane & 3;
#pragma unroll
    for (int mi = 0; mi < 4; mi++) {
#pragma unroll
        for (int ni = 0; ni < 4; ni++) {
            int n = n0 + wn * 32 + ni * 8 + tg * 2;
            bool nok = (n < HID);
#pragma unroll
            for (int half = 0; half < 2; half++) {
                int m = m0 + wm * 64 + mi * 16 + gid + half * 8;
                float v0 = acc[mi][ni][half * 2 + 0];
                float v1 = acc[mi][ni][half * 2 + 1];
                bool mok = (m < M);
                if (mok && nok) {
                    if (DO_BIAS) { v0 += bias[n]; v1 += bias[n + 1]; }
                    if (DO_SSP)  { v0 = ssp_f(v0); v1 = ssp_f(v1); }
                    if (DO_RSCALE) { float rs = rowscale[m]; v0 *= rs; v1 *= rs; }
                    float* cp = Cf + (size_t)m * HID + n;
                    if (OUTM == 0) {
                        *(float2*)cp = make_float2(v0, v1);
                    } else if (OUTM == 2) {
                        float2 o = *(float2*)cp;
                        v0 += o.x; v1 += o.y;
                        *(float2*)cp = make_float2(v0, v1);
                    }
                } else {
                    v0 = 0.0f; v1 = 0.0f;
                }
                if (OUTM >= 1) {
                    unsigned short h0, l0, h1, l1;
                    split_bf(v0, h0, l0);
                    split_bf(v1, h1, l1);
                    *(uint32_t*)((unsigned short*)Ph + (size_t)m * KP + n) =
                        (uint32_t)h0 | ((uint32_t)h1 << 16);
                    *(uint32_t*)((unsigned short*)Pl + (size_t)m * KP + n) =
                        (uint32_t)l0 | ((uint32_t)l1 << 16);
                }
            }
        }
    }
}

// ---------------------------------------------------------------------------
// CSR aggregation: 4 nodes per 640-thread block, pipelined edge loop.
// ---------------------------------------------------------------------------
__global__ __launch_bounds__(640)
void agg_kernel(const float* __restrict__ x, const float* __restrict__ tab,
                const int* __restrict__ ei,
                __nv_bfloat16* __restrict__ Ph, __nv_bfloat16* __restrict__ Pl) {
    int c = blockIdx.x * 4 + (threadIdx.x / 160);
    int lane = threadIdx.x % 160;
    if (lane >= HID / 4 || c >= NN) return;
    int s = g_off[c], epd = g_off[c + 1];
    float4 acc = make_float4(0.f, 0.f, 0.f, 0.f);
    const float* xp = x + 4 * lane;
    const float* tp = tab + 4 * lane;
    int r = 0, i0 = 0; float f = 0.f;
    if (s < epd) {
        int e = g_csr[s];
        r = ei[e]; i0 = g_ei0[e]; f = g_efr[e];
    }
    for (int j = s; j < epd; j++) {
        float4 xv = *(const float4*)(xp + (size_t)r * HID);
        float4 w0 = *(const float4*)(tp + (size_t)i0 * HID);
        float4 w1 = *(const float4*)(tp + (size_t)(i0 + 1) * HID);
        int rn = r, i0n = i0; float fn = f;
        if (j + 1 < epd) {
            int en = g_csr[j + 1];
            rn = ei[en]; i0n = g_ei0[en]; fn = g_efr[en];
        }
        acc.x += xv.x * fmaf(f, w1.x - w0.x, w0.x);
        acc.y += xv.y * fmaf(f, w1.y - w0.y, w0.y);
        acc.z += xv.z * fmaf(f, w1.z - w0.z, w0.z);
        acc.w += xv.w * fmaf(f, w1.w - w0.w, w0.w);
        r = rn; i0 = i0n; f = fn;
    }
    unsigned short h[4], l[4];
    split_bf(acc.x, h[0], l[0]);
    split_bf(acc.y, h[1], l[1]);
    split_bf(acc.z, h[2], l[2]);
    split_bf(acc.w, h[3], l[3]);
    uint2 uh, ul;
    uh.x = (uint32_t)h[0] | ((uint32_t)h[1] << 16);
    uh.y = (uint32_t)h[2] | ((uint32_t)h[3] << 16);
    ul.x = (uint32_t)l[0] | ((uint32_t)l[1] << 16);
    ul.y = (uint32_t)l[2] | ((uint32_t)l[3] << 16);
    *(uint2*)((unsigned short*)Ph + (size_t)c * KP + 4 * lane) = uh;
    *(uint2*)((unsigned short*)Pl + (size_t)c * KP + 4 * lane) = ul;
}

// ---------------------------------------------------------------------------
// Launch
// ---------------------------------------------------------------------------
extern "C" void kernel_launch(void* const* d_in, const int* in_sizes, int n_in,
                              void* d_out, int out_size) {
    const int*   z      = (const int*)  d_in[0];
    const float* pos    = (const float*)d_in[1];
    const int*   ei     = (const int*)  d_in[2];
    const float* emb    = (const float*)d_in[3];
    const float* mlp1_w = (const float*)d_in[4];
    const float* mlp1_b = (const float*)d_in[5];
    const float* mlp2_w = (const float*)d_in[6];
    const float* mlp2_b = (const float*)d_in[7];
    const float* lin1_w = (const float*)d_in[8];
    const float* lin2_w = (const float*)d_in[9];
    const float* lin2_b = (const float*)d_in[10];
    const float* lin_w  = (const float*)d_in[11];
    const float* lin_b  = (const float*)d_in[12];
    float* h = (float*)d_out;

    cudaFuncSetAttribute((const void*)hgemm<1,1,0,1>, cudaFuncAttributeMaxDynamicSharedMemorySize, SMEM_BYTES);
    cudaFuncSetAttribute((const void*)hgemm<1,0,1,0>, cudaFuncAttributeMaxDynamicSharedMemorySize, SMEM_BYTES);
    cudaFuncSetAttribute((const void*)hgemm<0,0,0,0>, cudaFuncAttributeMaxDynamicSharedMemorySize, SMEM_BYTES);
    cudaFuncSetAttribute((const void*)hgemm<1,0,0,2>, cudaFuncAttributeMaxDynamicSharedMemorySize, SMEM_BYTES);

    __nv_bfloat16 *eah, *eal, *t1h, *t1l, *hh, *hl, *agh, *agl, *x2h, *x2l, *w1h, *w1l, *wbh, *wbl;
    float *tab, *x, *Ct;
    int *cnt;
    cudaGetSymbolAddress((void**)&eah, g_ea_h); cudaGetSymbolAddress((void**)&eal, g_ea_l);
    cudaGetSymbolAddress((void**)&t1h, g_T1_h); cudaGetSymbolAddress((void**)&t1l, g_T1_l);
    cudaGetSymbolAddress((void**)&hh,  g_h_h);  cudaGetSymbolAddress((void**)&hl,  g_h_l);
    cudaGetSymbolAddress((void**)&agh, g_ag_h); cudaGetSymbolAddress((void**)&agl, g_ag_l);
    cudaGetSymbolAddress((void**)&x2h, g_x2_h); cudaGetSymbolAddress((void**)&x2l, g_x2_l);
    cudaGetSymbolAddress((void**)&w1h, g_w1_h); cudaGetSymbolAddress((void**)&w1l, g_w1_l);
    cudaGetSymbolAddress((void**)&wbh, g_wb_h); cudaGetSymbolAddress((void**)&wbl, g_wb_l);
    cudaGetSymbolAddress((void**)&tab, g_tab);  cudaGetSymbolAddress((void**)&x,   g_x);
    cudaGetSymbolAddress((void**)&Ct,  g_Ct);   cudaGetSymbolAddress((void**)&cnt, g_cnt);

    // Prologue
    cudaMemsetAsync(cnt, 0, NN * sizeof(int));
    prologue_kernel<<<B_TAB + B_EDGE + B_INIT, 256>>>(z, emb, pos, ei, h);
    csr_scan_kernel<<<1, 1024>>>();
    csr_place_kernel<<<(NE + 127) / 128, 128>>>(ei);
    {
        dim3 gW((600 * KP + 255) / 256, 1, NITR * 4);
        split_wb_kernel<<<gW, 256>>>(mlp2_w, lin1_w, lin2_w, lin_w);
        dim3 gW1((600 * KP1 + 255) / 256, 1, NITR);
        split_w1_kernel<<<gW1, 256>>>(mlp1_w);
    }
    // All-iteration filter tables (z = iteration); 240 blocks each = 1 wave
    {
        dim3 gT(5, GT / 128, NITR);
        hgemm<1,1,0,1><<<gT, 256, SMEM_BYTES>>>(eah, eal, w1h, w1l,
            mlp1_b, nullptr, nullptr, t1h, t1l, GT, KP1, KP1,
            0, (size_t)640 * KP1, HID, 0, (size_t)GT * KP);
        hgemm<1,0,1,0><<<gT, 256, SMEM_BYTES>>>(t1h, t1l, wbh, wbl,
            mlp2_b, Ct, tab, nullptr, nullptr, GT, KC, KP,
            (size_t)GT * KP, (size_t)4 * 640 * KP, HID, (size_t)GT * HID, 0);
    }

    dim3 gN(5, NPAD / 128, 1);   // 5 x 79 = 395 tiles

    for (int it = 0; it < NITR; it++) {
        const float* l2b = lin2_b + (size_t)it * HID;
        const float* lb  = lin_b  + (size_t)it * HID;
        __nv_bfloat16* l1wh = wbh + ((size_t)it * 4 + 1) * 640 * KP;
        __nv_bfloat16* l1wl = wbl + ((size_t)it * 4 + 1) * 640 * KP;
        __nv_bfloat16* l2wh = wbh + ((size_t)it * 4 + 2) * 640 * KP;
        __nv_bfloat16* l2wl = wbl + ((size_t)it * 4 + 2) * 640 * KP;
        __nv_bfloat16* lwh  = wbh + ((size_t)it * 4 + 3) * 640 * KP;
        __nv_bfloat16* lwl  = wbl + ((size_t)it * 4 + 3) * 640 * KP;

        // x = h @ l1w^T -> fp32
        hgemm<0,0,0,0><<<gN, 256, SMEM_BYTES>>>(hh, hl, l1wh, l1wl,
            nullptr, nullptr, x, nullptr, nullptr, NN, KC, KP, 0, 0, 0, 0, 0);
        // agg planes = CSR segment sum of x[row]*lerp(tab[it])
        agg_kernel<<<(NN + 3) / 4, 640>>>(x, tab + (size_t)it * GT * HID, ei, agh, agl);
        // x2 = ssp(agg @ l2w^T + l2b) -> planes
        hgemm<1,1,0,1><<<gN, 256, SMEM_BYTES>>>(agh, agl, l2wh, l2wl,
            l2b, nullptr, nullptr, x2h, x2l, NN, KC, KP, 0, 0, 0, 0, 0);
        // h += x2 @ lw^T + lb ; refresh h planes
        hgemm<1,0,0,2><<<gN, 256, SMEM_BYTES>>>(x2h, x2l, lwh, lwl,
            lb, nullptr, h, hh, hl, NN, KC, KP, 0, 0, 0, 0, 0);
    }
}

// round 11
// speedup vs baseline: 1.0855x; 1.0855x over previous
#include <cuda_runtime.h>
#include <cuda_bf16.h>
#include <math.h>
#include <stdint.h>

// Problem constants
#define NN   10000
#define NE   100000
#define HID  600
#define NGS  50
#define NITR 6
#define NZ   100        // embedding table rows

#define KP   640        // plane row stride (elements)
#define KC   608        // K compute extent (19 chunks of 32; cols 600..607 zero)
#define KP1  64         // padded gaussian K
#define NPAD 10112      // 79*128
#define GT   1024       // filter table resolution
#define DMAX 13.86f     // max possible distance: 8*sqrt(3)=13.8564
#define SMEM_BYTES (3 * 32768)

// ---------------------------------------------------------------------------
// Scratch (__device__ globals; zero-initialized at module load)
// ---------------------------------------------------------------------------
__device__ __align__(256) __nv_bfloat16 g_ea_h[(size_t)GT * KP1];
__device__ __align__(256) __nv_bfloat16 g_ea_l[(size_t)GT * KP1];
__device__ __align__(256) __nv_bfloat16 g_T1_h[(size_t)NITR * GT * KP];
__device__ __align__(256) __nv_bfloat16 g_T1_l[(size_t)NITR * GT * KP];
__device__ __align__(256) __nv_bfloat16 g_h_h [(size_t)NPAD * KP];
__device__ __align__(256) __nv_bfloat16 g_h_l [(size_t)NPAD * KP];
__device__ __align__(256) __nv_bfloat16 g_ag_h[(size_t)NPAD * KP];
__device__ __align__(256) __nv_bfloat16 g_ag_l[(size_t)NPAD * KP];
__device__ __align__(256) __nv_bfloat16 g_x2_h[(size_t)NPAD * KP];
__device__ __align__(256) __nv_bfloat16 g_x2_l[(size_t)NPAD * KP];
__device__ __align__(256) __nv_bfloat16 g_em_h[(size_t)128 * KP];   // emb planes
__device__ __align__(256) __nv_bfloat16 g_em_l[(size_t)128 * KP];
__device__ __align__(256) __nv_bfloat16 g_w1_h[(size_t)NITR * 640 * KP1];
__device__ __align__(256) __nv_bfloat16 g_w1_l[(size_t)NITR * 640 * KP1];
__device__ __align__(256) __nv_bfloat16 g_wb_h[(size_t)NITR * 4 * 640 * KP];
__device__ __align__(256) __nv_bfloat16 g_wb_l[(size_t)NITR * 4 * 640 * KP];
__device__ __align__(256) float g_tab [(size_t)NITR * GT * HID];  // filter tables
__device__ float g_x   [(size_t)NN * HID];
__device__ float g_xe  [(size_t)NZ * HID];   // emb @ l1w0^T
__device__ float g_Ct  [GT];
__device__ int   g_ei0 [NE];
__device__ float g_efr [NE];
// CSR (by target col)
__device__ int   g_cnt [NN];
__device__ int   g_off [NN + 1];
__device__ int   g_rank[NE];
__device__ int   g_csr [NE];

// ---------------------------------------------------------------------------
// Helpers
// ---------------------------------------------------------------------------
__device__ __forceinline__ uint32_t smem_u32(const void* p) {
    uint32_t a;
    asm("{ .reg .u64 t; cvta.to.shared.u64 t, %1; cvt.u32.u64 %0, t; }" : "=r"(a) : "l"(p));
    return a;
}
__device__ __forceinline__ void ldsm4(uint32_t (&r)[4], uint32_t addr) {
    asm volatile("ldmatrix.sync.aligned.m8n8.x4.shared.b16 {%0,%1,%2,%3}, [%4];"
                 : "=r"(r[0]), "=r"(r[1]), "=r"(r[2]), "=r"(r[3]) : "r"(addr));
}
__device__ __forceinline__ void mma16816(float (&d)[4], const uint32_t (&a)[4],
                                         uint32_t b0, uint32_t b1) {
    asm volatile("mma.sync.aligned.m16n8k16.row.col.f32.bf16.bf16.f32 "
                 "{%0,%1,%2,%3}, {%4,%5,%6,%7}, {%8,%9}, {%0,%1,%2,%3};"
                 : "+f"(d[0]), "+f"(d[1]), "+f"(d[2]), "+f"(d[3])
                 : "r"(a[0]), "r"(a[1]), "r"(a[2]), "r"(a[3]), "r"(b0), "r"(b1));
}
__device__ __forceinline__ void cpa16(uint32_t dst, const void* src) {
    asm volatile("cp.async.cg.shared.global [%0], [%1], 16;" :: "r"(dst), "l"(src));
}
__device__ __forceinline__ float ssp_f(float v) {
    float av = fabsf(v);
    return fmaxf(v, 0.0f) + log1pf(expf(-av)) - 0.69314718055994530942f;
}
__device__ __forceinline__ void split_bf(float v, unsigned short& h, unsigned short& l) {
    __nv_bfloat16 hi = __float2bfloat16(v);
    __nv_bfloat16 lo = __float2bfloat16(v - __bfloat162float(hi));
    h = __bfloat16_as_ushort(hi);
    l = __bfloat16_as_ushort(lo);
}
// split 4 values -> packed uint2 hi / uint2 lo
__device__ __forceinline__ void split_bf4(const float* v, uint2& uh, uint2& ul) {
    unsigned short h[4], l[4];
#pragma unroll
    for (int j = 0; j < 4; j++) split_bf(v[j], h[j], l[j]);
    uh.x = (uint32_t)h[0] | ((uint32_t)h[1] << 16);
    uh.y = (uint32_t)h[2] | ((uint32_t)h[3] << 16);
    ul.x = (uint32_t)l[0] | ((uint32_t)l[1] << 16);
    ul.y = (uint32_t)l[2] | ((uint32_t)l[3] << 16);
}

// ---------------------------------------------------------------------------
// Fused prologue: (a) table geometry, (b) edge prep, (c) emb-plane split,
// (d) h init + planes. Vectorized 4-wide where possible.
// ---------------------------------------------------------------------------
#define B_TAB  (GT / 256)                        // 4
#define B_EDGE ((NE + 255) / 256)                // 391
#define B_EMB  ((128 * KP) / 1024)               // 80
#define B_INIT ((NN * KP) / 1024)                // 6250

__global__ void prologue_kernel(const int* __restrict__ z, const float* __restrict__ emb,
                                const float* __restrict__ pos, const int* __restrict__ ei,
                                float* __restrict__ hout) {
    int bx = blockIdx.x;
    if (bx < B_TAB) {
        int g = bx * 256 + threadIdx.x;
        float d = (float)g * (DMAX / (float)(GT - 1));
        g_Ct[g] = 0.5f * (cosf(d * (float)(M_PI / 10.0)) + 1.0f);
        const float step  = 10.0f / 49.0f;
        const float coeff = -0.5f / (step * step);
        unsigned short* eh = (unsigned short*)g_ea_h + (size_t)g * KP1;
        unsigned short* el = (unsigned short*)g_ea_l + (size_t)g * KP1;
#pragma unroll 8
        for (int k = 0; k < KP1; k++) {
            float v = 0.0f;
            if (k < NGS) { float t = d - step * (float)k; v = expf(coeff * t * t); }
            unsigned short h, l; split_bf(v, h, l);
            eh[k] = h; el[k] = l;
        }
    } else if (bx < B_TAB + B_EDGE) {
        int e = (bx - B_TAB) * 256 + threadIdx.x;
        if (e >= NE) return;
        int r = ei[e], c = ei[NE + e];
        float dx = pos[3*r+0] - pos[3*c+0];
        float dy = pos[3*r+1] - pos[3*c+1];
        float dz = pos[3*r+2] - pos[3*c+2];
        float d = sqrtf(dx*dx + dy*dy + dz*dz);
        float t = d * ((float)(GT - 1) / DMAX);
        int i0 = (int)t;
        if (i0 > GT - 2) i0 = GT - 2;
        g_ei0[e] = i0;
        g_efr[e] = t - (float)i0;
        g_rank[e] = atomicAdd(&g_cnt[c], 1);
    } else if (bx < B_TAB + B_EDGE + B_EMB) {
        long i = ((long)(bx - B_TAB - B_EDGE) * 256 + threadIdx.x) * 4;
        int r = (int)(i / KP), k = (int)(i - (long)r * KP);
        float v[4] = {0.f, 0.f, 0.f, 0.f};
        if (r < NZ && k < HID) *(float4*)v = *(const float4*)(emb + (size_t)r * HID + k);
        uint2 uh, ul; split_bf4(v, uh, ul);
        *(uint2*)((unsigned short*)g_em_h + i) = uh;
        *(uint2*)((unsigned short*)g_em_l + i) = ul;
    } else {
        long i = ((long)(bx - B_TAB - B_EDGE - B_EMB) * 256 + threadIdx.x) * 4;
        int n = (int)(i / KP), k = (int)(i - (long)n * KP);
        float v[4] = {0.f, 0.f, 0.f, 0.f};
        if (k < HID) {
            *(float4*)v = *(const float4*)(emb + (size_t)z[n] * HID + k);
            *(float4*)(hout + (size_t)n * HID + k) = *(float4*)v;
        }
        uint2 uh, ul; split_bf4(v, uh, ul);
        *(uint2*)((unsigned short*)g_h_h + i) = uh;
        *(uint2*)((unsigned short*)g_h_l + i) = ul;
    }
}

// Exclusive scan of g_cnt -> g_off (single block, 1024 threads)
__global__ __launch_bounds__(1024)
void csr_scan_kernel() {
    __shared__ int part[1024];
    int t = threadIdx.x;
    int base = t * 10;
    int loc[10];
    int s = 0;
#pragma unroll
    for (int i = 0; i < 10; i++) {
        int idx = base + i;
        loc[i] = s;
        s += (idx < NN) ? g_cnt[idx] : 0;
    }
    part[t] = s;
    __syncthreads();
    for (int off = 1; off < 1024; off <<= 1) {
        int v = (t >= off) ? part[t - off] : 0;
        __syncthreads();
        if (t >= off) part[t] += v;
        __syncthreads();
    }
    int pre = (t > 0) ? part[t - 1] : 0;
#pragma unroll
    for (int i = 0; i < 10; i++) {
        int idx = base + i;
        if (idx < NN) g_off[idx] = pre + loc[i];
    }
    if (t == 1023) g_off[NN] = part[1023];
}

__global__ void csr_place_kernel(const int* __restrict__ ei) {
    int e = blockIdx.x * blockDim.x + threadIdx.x;
    if (e >= NE) return;
    int c = ei[NE + e];
    g_csr[g_off[c] + g_rank[e]] = e;
}

// Batched 4-wide split of the 24 HID x HID weights (z = it*4 + wix)
__global__ void split_wb_kernel(const float* __restrict__ w2, const float* __restrict__ l1,
                                const float* __restrict__ l2, const float* __restrict__ lw) {
    int zz = blockIdx.z;
    int wix = zz & 3, it = zz >> 2;
    const float* src = ((wix == 0) ? w2 : (wix == 1) ? l1 : (wix == 2) ? l2 : lw)
                       + (size_t)it * HID * HID;
    unsigned short* dh = (unsigned short*)g_wb_h + (size_t)zz * 640 * KP;
    unsigned short* dl = (unsigned short*)g_wb_l + (size_t)zz * 640 * KP;
    long i = ((long)blockIdx.x * blockDim.x + threadIdx.x) * 4;
    if (i >= (long)600 * KP) return;
    int r = (int)(i / KP), k = (int)(i - (long)r * KP);
    float v[4] = {0.f, 0.f, 0.f, 0.f};
    if (k < HID) *(float4*)v = *(const float4*)(src + (size_t)r * HID + k);
    uint2 uh, ul; split_bf4(v, uh, ul);
    *(uint2*)(dh + i) = uh;
    *(uint2*)(dl + i) = ul;
}

// Batched split of the 6 mlp1 weights (z = it); scalar (tiny, NGS=50 edge)
__global__ void split_w1_kernel(const float* __restrict__ w1) {
    int it = blockIdx.z;
    const float* src = w1 + (size_t)it * HID * NGS;
    unsigned short* dh = (unsigned short*)g_w1_h + (size_t)it * 640 * KP1;
    unsigned short* dl = (unsigned short*)g_w1_l + (size_t)it * 640 * KP1;
    long i = blockIdx.x * (long)blockDim.x + threadIdx.x;
    if (i >= (long)600 * KP1) return;
    int r = (int)(i / KP1), k = (int)(i - (long)r * KP1);
    float v = (k < NGS) ? src[(size_t)r * NGS + k] : 0.0f;
    unsigned short h, l; split_bf(v, h, l);
    dh[i] = h; dl[i] = l;
}

// x[n] = xe[z[n]] (iteration-0 x via embedding table), float4 per thread
__global__ void xgather_kernel(const int* __restrict__ z, const float* __restrict__ xe,
                               float* __restrict__ x) {
    long i = ((long)blockIdx.x * blockDim.x + threadIdx.x) * 4;
    if (i >= (long)NN * HID) return;
    int n = (int)(i / HID), k = (int)(i - (long)n * HID);
    *(float4*)(x + (size_t)n * HID + k) = *(const float4*)(xe + (size_t)z[n] * HID + k);
}

// ---------------------------------------------------------------------------
// bf16x3 HMMA GEMM, 128x128 tile, 2 CTAs/SM, 3-stage pipeline (R7 exact)
// out[m,n] = sum_k A[m,k]*B[n,k];  Kc = compute extent, ldA = plane row stride
// OUTM: 0 = fp32 out; 1 = bf16 planes out; 2 = fp32 residual-add + planes out
// ---------------------------------------------------------------------------
template <int DO_BIAS, int DO_SSP, int DO_RSCALE, int OUTM>
__global__ __launch_bounds__(256, 2)
void hgemm(const __nv_bfloat16* __restrict__ Ah, const __nv_bfloat16* __restrict__ Al,
           const __nv_bfloat16* __restrict__ Bh, const __nv_bfloat16* __restrict__ Bl,
           const float* __restrict__ bias, const float* __restrict__ rowscale,
           float* __restrict__ Cf,
           __nv_bfloat16* __restrict__ Ph, __nv_bfloat16* __restrict__ Pl,
           int M, int Kc, int ldA,
           size_t aZ, size_t bZ, size_t biasZ, size_t cZ, size_t pZ) {
    extern __shared__ char smem[];
    const uint32_t sb = smem_u32(smem);
    const int tid = threadIdx.x, lane = tid & 31, wid = tid >> 5;
    const int wm = wid >> 2, wn = wid & 3;
    const int m0 = blockIdx.y * 128, n0 = blockIdx.x * 128;
    const int zz = blockIdx.z;

    Ah += (size_t)zz * aZ;  Al += (size_t)zz * aZ;
    Bh += (size_t)zz * bZ;  Bl += (size_t)zz * bZ;
    if (DO_BIAS)   bias += (size_t)zz * biasZ;
    if (OUTM != 1) Cf   += (size_t)zz * cZ;
    if (OUTM >= 1) { Ph += (size_t)zz * pZ; Pl += (size_t)zz * pZ; }

    float acc[4][4][4];
#pragma unroll
    for (int a = 0; a < 4; a++)
#pragma unroll
        for (int b = 0; b < 4; b++)
#pragma unroll
            for (int c = 0; c < 4; c++) acc[a][b][c] = 0.0f;

    const __nv_bfloat16* srcs[4] = { Ah, Al, Bh, Bl };
    const int lr = tid >> 2;
    const int lc = tid & 3;

#define PREFETCH(chunk, stg) do {                                              \
        uint32_t sbase = sb + (stg) * 32768;                                   \
        int k0 = (chunk) * 32;                                                 \
        _Pragma("unroll")                                                      \
        for (int t = 0; t < 4; t++) {                                          \
            const __nv_bfloat16* s = srcs[t];                                  \
            int rb = (t < 2) ? m0 : n0;                                        \
            _Pragma("unroll")                                                  \
            for (int i = 0; i < 2; i++) {                                      \
                int r = i * 64 + lr;                                           \
                const void* g = s + (size_t)(rb + r) * ldA + k0 + lc * 8;      \
                uint32_t d = sbase + t * 8192 + r * 64 +                       \
                             ((lc ^ ((r >> 1) & 3)) * 16);                     \
                cpa16(d, g);                                                   \
            }                                                                  \
        }                                                                      \
        asm volatile("cp.async.commit_group;" ::: "memory");                   \
    } while (0)

    const int nc = Kc >> 5;
    PREFETCH(0, 0);
    if (nc > 1) PREFETCH(1, 1);
    for (int ch = 0; ch < nc; ch++) {
        int stg = ch % 3;
        if (ch + 1 < nc) {
            asm volatile("cp.async.wait_group 1;" ::: "memory");
        } else {
            asm volatile("cp.async.wait_group 0;" ::: "memory");
        }
        __syncthreads();
        if (ch + 2 < nc) PREFETCH(ch + 2, (ch + 2) % 3);

        uint32_t Abase = sb + stg * 32768;
        uint32_t Bbase = Abase + 16384;
#pragma unroll
        for (int ks = 0; ks < 2; ks++) {
            int arow = wm * 64 + (lane & 15);
            int brow = wn * 32 + (lane & 15);
            int cch  = ks * 2 + (lane >> 4);
            uint32_t af[4][4], bhf[2][4], blf[2][4];
#pragma unroll
            for (int p = 0; p < 2; p++) {
                int r = brow + p * 16;
                ldsm4(bhf[p], Bbase + r * 64 + ((cch ^ ((r >> 1) & 3)) * 16));
            }
#pragma unroll
            for (int p = 0; p < 2; p++) {
                int r = brow + p * 16;
                ldsm4(blf[p], Bbase + 8192 + r * 64 + ((cch ^ ((r >> 1) & 3)) * 16));
            }
#pragma unroll
            for (int mi = 0; mi < 4; mi++) {
                int r = arow + mi * 16;
                ldsm4(af[mi], Abase + r * 64 + ((cch ^ ((r >> 1) & 3)) * 16));
            }
#pragma unroll
            for (int mi = 0; mi < 4; mi++)
#pragma unroll
                for (int ni = 0; ni < 4; ni++)
                    mma16816(acc[mi][ni], af[mi], bhf[ni >> 1][ni & 1], bhf[ni >> 1][(ni & 1) + 2]);
#pragma unroll
            for (int mi = 0; mi < 4; mi++)
#pragma unroll
                for (int ni = 0; ni < 4; ni++)
                    mma16816(acc[mi][ni], af[mi], blf[ni >> 1][ni & 1], blf[ni >> 1][(ni & 1) + 2]);
#pragma unroll
            for (int mi = 0; mi < 4; mi++) {
                int r = arow + mi * 16;
                ldsm4(af[mi], Abase + 8192 + r * 64 + ((cch ^ ((r >> 1) & 3)) * 16));
            }
#pragma unroll
            for (int mi = 0; mi < 4; mi++)
#pragma unroll
                for (int ni = 0; ni < 4; ni++)
                    mma16816(acc[mi][ni], af[mi], bhf[ni >> 1][ni & 1], bhf[ni >> 1][(ni & 1) + 2]);
        }
        __syncthreads();
    }
#undef PREFETCH

    const int gid = lane >> 2, tg = lane & 3;
#pragma unroll
    for (int mi = 0; mi < 4; mi++) {
#pragma unroll
        for (int ni = 0; ni < 4; ni++) {
            int n = n0 + wn * 32 + ni * 8 + tg * 2;
            bool nok = (n < HID);
#pragma unroll
            for (int half = 0; half < 2; half++) {
                int m = m0 + wm * 64 + mi * 16 + gid + half * 8;
                float v0 = acc[mi][ni][half * 2 + 0];
                float v1 = acc[mi][ni][half * 2 + 1];
                bool mok = (m < M);
                if (mok && nok) {
                    if (DO_BIAS) { v0 += bias[n]; v1 += bias[n + 1]; }
                    if (DO_SSP)  { v0 = ssp_f(v0); v1 = ssp_f(v1); }
                    if (DO_RSCALE) { float rs = rowscale[m]; v0 *= rs; v1 *= rs; }
                    float* cp = Cf + (size_t)m * HID + n;
                    if (OUTM == 0) {
                        *(float2*)cp = make_float2(v0, v1);
                    } else if (OUTM == 2) {
                        float2 o = *(float2*)cp;
                        v0 += o.x; v1 += o.y;
                        *(float2*)cp = make_float2(v0, v1);
                    }
                } else {
                    v0 = 0.0f; v1 = 0.0f;
                }
                if (OUTM >= 1) {
                    unsigned short h0, l0, h1, l1;
                    split_bf(v0, h0, l0);
                    split_bf(v1, h1, l1);
                    *(uint32_t*)((unsigned short*)Ph + (size_t)m * KP + n) =
                        (uint32_t)h0 | ((uint32_t)h1 << 16);
                    *(uint32_t*)((unsigned short*)Pl + (size_t)m * KP + n) =
                        (uint32_t)l0 | ((uint32_t)l1 << 16);
                }
            }
        }
    }
}

// ---------------------------------------------------------------------------
// CSR aggregation (R7-exact): 1 node per 160-thread block, pipelined edges.
// ---------------------------------------------------------------------------
__global__ __launch_bounds__(160)
void agg_kernel(const float* __restrict__ x, const float* __restrict__ tab,
                const int* __restrict__ ei,
                __nv_bfloat16* __restrict__ Ph, __nv_bfloat16* __restrict__ Pl) {
    int c = blockIdx.x;
    int lane = threadIdx.x;
    if (lane >= HID / 4) return;
    int s = g_off[c], epd = g_off[c + 1];
    float4 acc = make_float4(0.f, 0.f, 0.f, 0.f);
    const float* xp = x + 4 * lane;
    const float* tp = tab + 4 * lane;
    int r = 0, i0 = 0; float f = 0.f;
    if (s < epd) {
        int e = g_csr[s];
        r = ei[e]; i0 = g_ei0[e]; f = g_efr[e];
    }
    for (int j = s; j < epd; j++) {
        float4 xv = *(const float4*)(xp + (size_t)r * HID);
        float4 w0 = *(const float4*)(tp + (size_t)i0 * HID);
        float4 w1 = *(const float4*)(tp + (size_t)(i0 + 1) * HID);
        int rn = r, i0n = i0; float fn = f;
        if (j + 1 < epd) {
            int en = g_csr[j + 1];
            rn = ei[en]; i0n = g_ei0[en]; fn = g_efr[en];
        }
        acc.x += xv.x * fmaf(f, w1.x - w0.x, w0.x);
        acc.y += xv.y * fmaf(f, w1.y - w0.y, w0.y);
        acc.z += xv.z * fmaf(f, w1.z - w0.z, w0.z);
        acc.w += xv.w * fmaf(f, w1.w - w0.w, w0.w);
        r = rn; i0 = i0n; f = fn;
    }
    float av[4] = {acc.x, acc.y, acc.z, acc.w};
    uint2 uh, ul; split_bf4(av, uh, ul);
    *(uint2*)((unsigned short*)Ph + (size_t)c * KP + 4 * lane) = uh;
    *(uint2*)((unsigned short*)Pl + (size_t)c * KP + 4 * lane) = ul;
}

// ---------------------------------------------------------------------------
// Launch
// ---------------------------------------------------------------------------
extern "C" void kernel_launch(void* const* d_in, const int* in_sizes, int n_in,
                              void* d_out, int out_size) {
    const int*   z      = (const int*)  d_in[0];
    const float* pos    = (const float*)d_in[1];
    const int*   ei     = (const int*)  d_in[2];
    const float* emb    = (const float*)d_in[3];
    const float* mlp1_w = (const float*)d_in[4];
    const float* mlp1_b = (const float*)d_in[5];
    const float* mlp2_w = (const float*)d_in[6];
    const float* mlp2_b = (const float*)d_in[7];
    const float* lin1_w = (const float*)d_in[8];
    const float* lin2_w = (const float*)d_in[9];
    const float* lin2_b = (const float*)d_in[10];
    const float* lin_w  = (const float*)d_in[11];
    const float* lin_b  = (const float*)d_in[12];
    float* h = (float*)d_out;

    cudaFuncSetAttribute((const void*)hgemm<1,1,0,1>, cudaFuncAttributeMaxDynamicSharedMemorySize, SMEM_BYTES);
    cudaFuncSetAttribute((const void*)hgemm<1,0,1,0>, cudaFuncAttributeMaxDynamicSharedMemorySize, SMEM_BYTES);
    cudaFuncSetAttribute((const void*)hgemm<0,0,0,0>, cudaFuncAttributeMaxDynamicSharedMemorySize, SMEM_BYTES);
    cudaFuncSetAttribute((const void*)hgemm<1,0,0,2>, cudaFuncAttributeMaxDynamicSharedMemorySize, SMEM_BYTES);

    __nv_bfloat16 *eah, *eal, *t1h, *t1l, *hh, *hl, *agh, *agl, *x2h, *x2l;
    __nv_bfloat16 *emh, *eml, *w1h, *w1l, *wbh, *wbl;
    float *tab, *x, *xe, *Ct;
    int *cnt;
    cudaGetSymbolAddress((void**)&eah, g_ea_h); cudaGetSymbolAddress((void**)&eal, g_ea_l);
    cudaGetSymbolAddress((void**)&t1h, g_T1_h); cudaGetSymbolAddress((void**)&t1l, g_T1_l);
    cudaGetSymbolAddress((void**)&hh,  g_h_h);  cudaGetSymbolAddress((void**)&hl,  g_h_l);
    cudaGetSymbolAddress((void**)&agh, g_ag_h); cudaGetSymbolAddress((void**)&agl, g_ag_l);
    cudaGetSymbolAddress((void**)&x2h, g_x2_h); cudaGetSymbolAddress((void**)&x2l, g_x2_l);
    cudaGetSymbolAddress((void**)&emh, g_em_h); cudaGetSymbolAddress((void**)&eml, g_em_l);
    cudaGetSymbolAddress((void**)&w1h, g_w1_h); cudaGetSymbolAddress((void**)&w1l, g_w1_l);
    cudaGetSymbolAddress((void**)&wbh, g_wb_h); cudaGetSymbolAddress((void**)&wbl, g_wb_l);
    cudaGetSymbolAddress((void**)&tab, g_tab);  cudaGetSymbolAddress((void**)&x,   g_x);
    cudaGetSymbolAddress((void**)&xe,  g_xe);   cudaGetSymbolAddress((void**)&Ct,  g_Ct);
    cudaGetSymbolAddress((void**)&cnt, g_cnt);

    // 1-4: memset, splits, prologue
    cudaMemsetAsync(cnt, 0, NN * sizeof(int));
    {
        dim3 gW((600 * KP / 4 + 255) / 256, 1, NITR * 4);
        split_wb_kernel<<<gW, 256>>>(mlp2_w, lin1_w, lin2_w, lin_w);
        dim3 gW1((600 * KP1 + 255) / 256, 1, NITR);
        split_w1_kernel<<<gW1, 256>>>(mlp1_w);
    }
    prologue_kernel<<<B_TAB + B_EDGE + B_EMB + B_INIT, 256>>>(z, emb, pos, ei, h);
    // 5-6: table GEMMs (ncu -s 5 -c 1 captures #6 = the K=608 hgemm)
    {
        dim3 gT(5, GT / 128, NITR);   // 240 blocks = 1 wave
        hgemm<1,1,0,1><<<gT, 256, SMEM_BYTES>>>(eah, eal, w1h, w1l,
            mlp1_b, nullptr, nullptr, t1h, t1l, GT, KP1, KP1,
            0, (size_t)640 * KP1, HID, 0, (size_t)GT * KP);
        hgemm<1,0,1,0><<<gT, 256, SMEM_BYTES>>>(t1h, t1l, wbh, wbl,
            mlp2_b, Ct, tab, nullptr, nullptr, GT, KC, KP,
            (size_t)GT * KP, (size_t)4 * 640 * KP, HID, (size_t)GT * HID, 0);
    }
    // 7-8: iteration-0 x via embedding table: xe = emb @ l1w0^T; x = xe[z]
    {
        __nv_bfloat16* l1wh0 = wbh + (size_t)1 * 640 * KP;   // it=0, wix=1
        __nv_bfloat16* l1wl0 = wbl + (size_t)1 * 640 * KP;
        dim3 gZ(5, 1, 1);
        hgemm<0,0,0,0><<<gZ, 256, SMEM_BYTES>>>(emh, eml, l1wh0, l1wl0,
            nullptr, nullptr, xe, nullptr, nullptr, NZ, KC, KP, 0, 0, 0, 0, 0);
        xgather_kernel<<<(int)(((long)NN * HID / 4 + 255) / 256), 256>>>(z, xe, x);
    }
    // 9-10: CSR finalize
    csr_scan_kernel<<<1, 1024>>>();
    csr_place_kernel<<<(NE + 127) / 128, 128>>>(ei);

    dim3 gN(5, NPAD / 128, 1);   // 5 x 79 = 395 tiles

    for (int it = 0; it < NITR; it++) {
        const float* l2b = lin2_b + (size_t)it * HID;
        const float* lb  = lin_b  + (size_t)it * HID;
        __nv_bfloat16* l1wh = wbh + ((size_t)it * 4 + 1) * 640 * KP;
        __nv_bfloat16* l1wl = wbl + ((size_t)it * 4 + 1) * 640 * KP;
        __nv_bfloat16* l2wh = wbh + ((size_t)it * 4 + 2) * 640 * KP;
        __nv_bfloat16* l2wl = wbl + ((size_t)it * 4 + 2) * 640 * KP;
        __nv_bfloat16* lwh  = wbh + ((size_t)it * 4 + 3) * 640 * KP;
        __nv_bfloat16* lwl  = wbl + ((size_t)it * 4 + 3) * 640 * KP;

        if (it > 0) {
            // x = h @ l1w^T -> fp32  (iteration 0 handled via xe gather)
            hgemm<0,0,0,0><<<gN, 256, SMEM_BYTES>>>(hh, hl, l1wh, l1wl,
                nullptr, nullptr, x, nullptr, nullptr, NN, KC, KP, 0, 0, 0, 0, 0);
        }
        // agg planes = CSR segment sum of x[row]*lerp(tab[it])
        agg_kernel<<<NN, 160>>>(x, tab + (size_t)it * GT * HID, ei, agh, agl);
        // x2 = ssp(agg @ l2w^T + l2b) -> planes
        hgemm<1,1,0,1><<<gN, 256, SMEM_BYTES>>>(agh, agl, l2wh, l2wl,
            l2b, nullptr, nullptr, x2h, x2l, NN, KC, KP, 0, 0, 0, 0, 0);
        // h += x2 @ lw^T + lb ; refresh h planes
        hgemm<1,0,0,2><<<gN, 256, SMEM_BYTES>>>(x2h, x2l, lwh, lwl,
            lb, nullptr, h, hh, hl, NN, KC, KP, 0, 0, 0, 0, 0);
    }
}

// round 12
// speedup vs baseline: 1.8752x; 1.7275x over previous
#include <cuda_runtime.h>
#include <cuda_bf16.h>
#include <cuda_fp16.h>
#include <math.h>
#include <stdint.h>

// Problem constants
#define NN   10000
#define NE   100000
#define HID  600
#define NGS  50
#define NITR 6
#define NZ   100        // embedding table rows

#define KP   640        // plane row stride (elements)
#define KC   608        // K compute extent (19 chunks of 32)
#define KP1  64         // padded gaussian K
#define NPAD 10112      // 79*128
#define GT   1024       // filter table resolution
#define DMAX 13.86f
#define STG  16384      // stage = A(8KB) + B(8KB)
#define SMEM_BYTES (4 * STG)   // 4-stage pipeline, 64KB

// ---------------------------------------------------------------------------
// Scratch (__device__ globals; zero-initialized)
// ---------------------------------------------------------------------------
__device__ __align__(256) __half g_ea [(size_t)GT * KP1];
__device__ __align__(256) __half g_T1 [(size_t)NITR * GT * KP];
__device__ __align__(256) __half g_h  [(size_t)NPAD * KP];
__device__ __align__(256) __half g_ag [(size_t)NPAD * KP];
__device__ __align__(256) __half g_x2 [(size_t)NPAD * KP];
__device__ __align__(256) __half g_em [(size_t)128 * KP];
__device__ __align__(256) __half g_w1 [(size_t)NITR * 640 * KP1];
__device__ __align__(256) __half g_wb [(size_t)NITR * 4 * 640 * KP];
__device__ __align__(256) float g_tab [(size_t)NITR * GT * HID];
__device__ float g_x   [(size_t)NN * HID];
__device__ float g_xe  [(size_t)NZ * HID];
__device__ float g_Ct  [GT];
__device__ int   g_ei0 [NE];
__device__ float g_efr [NE];
__device__ int   g_cnt [NN];
__device__ int   g_off [NN + 1];
__device__ int   g_rank[NE];
__device__ int   g_csr [NE];

// ---------------------------------------------------------------------------
// Helpers
// ---------------------------------------------------------------------------
__device__ __forceinline__ uint32_t smem_u32(const void* p) {
    uint32_t a;
    asm("{ .reg .u64 t; cvta.to.shared.u64 t, %1; cvt.u32.u64 %0, t; }" : "=r"(a) : "l"(p));
    return a;
}
__device__ __forceinline__ void ldsm4(uint32_t (&r)[4], uint32_t addr) {
    asm volatile("ldmatrix.sync.aligned.m8n8.x4.shared.b16 {%0,%1,%2,%3}, [%4];"
                 : "=r"(r[0]), "=r"(r[1]), "=r"(r[2]), "=r"(r[3]) : "r"(addr));
}
__device__ __forceinline__ void mma16816h(float (&d)[4], const uint32_t (&a)[4],
                                          uint32_t b0, uint32_t b1) {
    asm volatile("mma.sync.aligned.m16n8k16.row.col.f32.f16.f16.f32 "
                 "{%0,%1,%2,%3}, {%4,%5,%6,%7}, {%8,%9}, {%0,%1,%2,%3};"
                 : "+f"(d[0]), "+f"(d[1]), "+f"(d[2]), "+f"(d[3])
                 : "r"(a[0]), "r"(a[1]), "r"(a[2]), "r"(a[3]), "r"(b0), "r"(b1));
}
__device__ __forceinline__ void cpa16(uint32_t dst, const void* src) {
    asm volatile("cp.async.cg.shared.global [%0], [%1], 16;" :: "r"(dst), "l"(src));
}
__device__ __forceinline__ float ssp_f(float v) {
    float av = fabsf(v);
    return fmaxf(v, 0.0f) + log1pf(expf(-av)) - 0.69314718055994530942f;
}
__device__ __forceinline__ uint32_t pack_h2(float a, float b) {
    __half2 p = __floats2half2_rn(a, b);
    return *(uint32_t*)&p;
}
__device__ __forceinline__ uint2 pack_h4(const float* v) {
    uint2 u;
    u.x = pack_h2(v[0], v[1]);
    u.y = pack_h2(v[2], v[3]);
    return u;
}

// ---------------------------------------------------------------------------
// Fused prologue: (a) table geometry, (b) edge prep, (c) emb conv, (d) h init
// ---------------------------------------------------------------------------
#define B_TAB  (GT / 256)                        // 4
#define B_EDGE ((NE + 255) / 256)                // 391
#define B_EMB  ((128 * KP) / 1024)               // 80
#define B_INIT ((NN * KP) / 1024)                // 6250

__global__ void prologue_kernel(const int* __restrict__ z, const float* __restrict__ emb,
                                const float* __restrict__ pos, const int* __restrict__ ei,
                                float* __restrict__ hout) {
    int bx = blockIdx.x;
    if (bx < B_TAB) {
        int g = bx * 256 + threadIdx.x;
        float d = (float)g * (DMAX / (float)(GT - 1));
        g_Ct[g] = 0.5f * (cosf(d * (float)(M_PI / 10.0)) + 1.0f);
        const float step  = 10.0f / 49.0f;
        const float coeff = -0.5f / (step * step);
        __half* eh = g_ea + (size_t)g * KP1;
#pragma unroll 8
        for (int k = 0; k < KP1; k++) {
            float v = 0.0f;
            if (k < NGS) { float t = d - step * (float)k; v = expf(coeff * t * t); }
            eh[k] = __float2half_rn(v);
        }
    } else if (bx < B_TAB + B_EDGE) {
        int e = (bx - B_TAB) * 256 + threadIdx.x;
        if (e >= NE) return;
        int r = ei[e], c = ei[NE + e];
        float dx = pos[3*r+0] - pos[3*c+0];
        float dy = pos[3*r+1] - pos[3*c+1];
        float dz = pos[3*r+2] - pos[3*c+2];
        float d = sqrtf(dx*dx + dy*dy + dz*dz);
        float t = d * ((float)(GT - 1) / DMAX);
        int i0 = (int)t;
        if (i0 > GT - 2) i0 = GT - 2;
        g_ei0[e] = i0;
        g_efr[e] = t - (float)i0;
        g_rank[e] = atomicAdd(&g_cnt[c], 1);
    } else if (bx < B_TAB + B_EDGE + B_EMB) {
        long i = ((long)(bx - B_TAB - B_EDGE) * 256 + threadIdx.x) * 4;
        int r = (int)(i / KP), k = (int)(i - (long)r * KP);
        float v[4] = {0.f, 0.f, 0.f, 0.f};
        if (r < NZ && k < HID) *(float4*)v = *(const float4*)(emb + (size_t)r * HID + k);
        *(uint2*)(g_em + i) = pack_h4(v);
    } else {
        long i = ((long)(bx - B_TAB - B_EDGE - B_EMB) * 256 + threadIdx.x) * 4;
        int n = (int)(i / KP), k = (int)(i - (long)n * KP);
        float v[4] = {0.f, 0.f, 0.f, 0.f};
        if (k < HID) {
            *(float4*)v = *(const float4*)(emb + (size_t)z[n] * HID + k);
            *(float4*)(hout + (size_t)n * HID + k) = *(float4*)v;
        }
        *(uint2*)(g_h + i) = pack_h4(v);
    }
}

// Exclusive scan of g_cnt -> g_off (single block)
__global__ __launch_bounds__(1024)
void csr_scan_kernel() {
    __shared__ int part[1024];
    int t = threadIdx.x;
    int base = t * 10;
    int loc[10];
    int s = 0;
#pragma unroll
    for (int i = 0; i < 10; i++) {
        int idx = base + i;
        loc[i] = s;
        s += (idx < NN) ? g_cnt[idx] : 0;
    }
    part[t] = s;
    __syncthreads();
    for (int off = 1; off < 1024; off <<= 1) {
        int v = (t >= off) ? part[t - off] : 0;
        __syncthreads();
        if (t >= off) part[t] += v;
        __syncthreads();
    }
    int pre = (t > 0) ? part[t - 1] : 0;
#pragma unroll
    for (int i = 0; i < 10; i++) {
        int idx = base + i;
        if (idx < NN) g_off[idx] = pre + loc[i];
    }
    if (t == 1023) g_off[NN] = part[1023];
}

__global__ void csr_place_kernel(const int* __restrict__ ei) {
    int e = blockIdx.x * blockDim.x + threadIdx.x;
    if (e >= NE) return;
    int c = ei[NE + e];
    g_csr[g_off[c] + g_rank[e]] = e;
}

// Batched 4-wide convert of 24 HID x HID weights (z = it*4 + wix)
__global__ void cvt_wb_kernel(const float* __restrict__ w2, const float* __restrict__ l1,
                              const float* __restrict__ l2, const float* __restrict__ lw) {
    int zz = blockIdx.z;
    int wix = zz & 3, it = zz >> 2;
    const float* src = ((wix == 0) ? w2 : (wix == 1) ? l1 : (wix == 2) ? l2 : lw)
                       + (size_t)it * HID * HID;
    __half* dh = g_wb + (size_t)zz * 640 * KP;
    long i = ((long)blockIdx.x * blockDim.x + threadIdx.x) * 4;
    if (i >= (long)600 * KP) return;
    int r = (int)(i / KP), k = (int)(i - (long)r * KP);
    float v[4] = {0.f, 0.f, 0.f, 0.f};
    if (k < HID) *(float4*)v = *(const float4*)(src + (size_t)r * HID + k);
    *(uint2*)(dh + i) = pack_h4(v);
}

// Batched convert of 6 mlp1 weights (z = it)
__global__ void cvt_w1_kernel(const float* __restrict__ w1) {
    int it = blockIdx.z;
    const float* src = w1 + (size_t)it * HID * NGS;
    __half* dh = g_w1 + (size_t)it * 640 * KP1;
    long i = blockIdx.x * (long)blockDim.x + threadIdx.x;
    if (i >= (long)600 * KP1) return;
    int r = (int)(i / KP1), k = (int)(i - (long)r * KP1);
    float v = (k < NGS) ? src[(size_t)r * NGS + k] : 0.0f;
    dh[i] = __float2half_rn(v);
}

// x[n] = xe[z[n]]
__global__ void xgather_kernel(const int* __restrict__ z, const float* __restrict__ xe,
                               float* __restrict__ x) {
    long i = ((long)blockIdx.x * blockDim.x + threadIdx.x) * 4;
    if (i >= (long)NN * HID) return;
    int n = (int)(i / HID), k = (int)(i - (long)n * HID);
    *(float4*)(x + (size_t)n * HID + k) = *(const float4*)(xe + (size_t)z[n] * HID + k);
}

// ---------------------------------------------------------------------------
// fp16 HMMA GEMM, 128x128 tile, 2 CTAs/SM, 4-stage cp.async pipeline
// out[m,n] = sum_k A[m,k]*B[n,k];  Kc = compute extent, ldA = row stride
// OUTM: 0 = fp32 out; 1 = fp16 plane out; 2 = fp32 residual-add + plane out
// ---------------------------------------------------------------------------
template <int DO_BIAS, int DO_SSP, int DO_RSCALE, int OUTM>
__global__ __launch_bounds__(256, 2)
void hgemm(const __half* __restrict__ A, const __half* __restrict__ B,
           const float* __restrict__ bias, const float* __restrict__ rowscale,
           float* __restrict__ Cf, __half* __restrict__ P,
           int M, int Kc, int ldA,
           size_t aZ, size_t bZ, size_t biasZ, size_t cZ, size_t pZ) {
    extern __shared__ char smem[];
    const uint32_t sb = smem_u32(smem);
    const int tid = threadIdx.x, lane = tid & 31, wid = tid >> 5;
    const int wm = wid >> 2, wn = wid & 3;          // 2x4 warp grid, 64x32 warp tile
    const int m0 = blockIdx.y * 128, n0 = blockIdx.x * 128;
    const int zz = blockIdx.z;

    A += (size_t)zz * aZ;
    B += (size_t)zz * bZ;
    if (DO_BIAS)   bias += (size_t)zz * biasZ;
    if (OUTM != 1) Cf   += (size_t)zz * cZ;
    if (OUTM >= 1) P    += (size_t)zz * pZ;

    float acc[4][4][4];
#pragma unroll
    for (int a = 0; a < 4; a++)
#pragma unroll
        for (int b = 0; b < 4; b++)
#pragma unroll
            for (int c = 0; c < 4; c++) acc[a][b][c] = 0.0f;

    const int lr = tid >> 2;
    const int lc = tid & 3;

#define PREFETCH(chunk, stg) do {                                              \
        uint32_t sbase = sb + (stg) * STG;                                     \
        int k0 = (chunk) * 32;                                                 \
        _Pragma("unroll")                                                      \
        for (int i = 0; i < 2; i++) {                                          \
            int r = i * 64 + lr;                                               \
            uint32_t sw = (uint32_t)((lc ^ ((r >> 1) & 3)) * 16);              \
            cpa16(sbase + r * 64 + sw,                                         \
                  A + (size_t)(m0 + r) * ldA + k0 + lc * 8);                   \
            cpa16(sbase + 8192 + r * 64 + sw,                                  \
                  B + (size_t)(n0 + r) * ldA + k0 + lc * 8);                   \
        }                                                                      \
        asm volatile("cp.async.commit_group;" ::: "memory");                   \
    } while (0)

    const int nc = Kc >> 5;
    PREFETCH(0, 0);
    if (nc > 1) PREFETCH(1, 1);
    if (nc > 2) PREFETCH(2, 2);
    for (int ch = 0; ch < nc; ch++) {
        int stg = ch & 3;
        if (ch + 2 < nc) {
            asm volatile("cp.async.wait_group 2;" ::: "memory");
        } else if (ch + 1 < nc) {
            asm volatile("cp.async.wait_group 1;" ::: "memory");
        } else {
            asm volatile("cp.async.wait_group 0;" ::: "memory");
        }
        __syncthreads();
        if (ch + 3 < nc) PREFETCH(ch + 3, (ch + 3) & 3);

        uint32_t Abase = sb + stg * STG;
        uint32_t Bbase = Abase + 8192;
#pragma unroll
        for (int ks = 0; ks < 2; ks++) {
            int arow = wm * 64 + (lane & 15);
            int brow = wn * 32 + (lane & 15);
            int cch  = ks * 2 + (lane >> 4);
            uint32_t af[4][4], bf[2][4];
#pragma unroll
            for (int p = 0; p < 2; p++) {
                int r = brow + p * 16;
                ldsm4(bf[p], Bbase + r * 64 + ((cch ^ ((r >> 1) & 3)) * 16));
            }
#pragma unroll
            for (int mi = 0; mi < 4; mi++) {
                int r = arow + mi * 16;
                ldsm4(af[mi], Abase + r * 64 + ((cch ^ ((r >> 1) & 3)) * 16));
            }
#pragma unroll
            for (int mi = 0; mi < 4; mi++)
#pragma unroll
                for (int ni = 0; ni < 4; ni++)
                    mma16816h(acc[mi][ni], af[mi], bf[ni >> 1][ni & 1], bf[ni >> 1][(ni & 1) + 2]);
        }
        __syncthreads();
    }
#undef PREFETCH

    const int gid = lane >> 2, tg = lane & 3;
#pragma unroll
    for (int mi = 0; mi < 4; mi++) {
#pragma unroll
        for (int ni = 0; ni < 4; ni++) {
            int n = n0 + wn * 32 + ni * 8 + tg * 2;
            bool nok = (n < HID);
#pragma unroll
            for (int half = 0; half < 2; half++) {
                int m = m0 + wm * 64 + mi * 16 + gid + half * 8;
                float v0 = acc[mi][ni][half * 2 + 0];
                float v1 = acc[mi][ni][half * 2 + 1];
                bool mok = (m < M);
                if (mok && nok) {
                    if (DO_BIAS) { v0 += bias[n]; v1 += bias[n + 1]; }
                    if (DO_SSP)  { v0 = ssp_f(v0); v1 = ssp_f(v1); }
                    if (DO_RSCALE) { float rs = rowscale[m]; v0 *= rs; v1 *= rs; }
                    float* cp = Cf + (size_t)m * HID + n;
                    if (OUTM == 0) {
                        *(float2*)cp = make_float2(v0, v1);
                    } else if (OUTM == 2) {
                        float2 o = *(float2*)cp;
                        v0 += o.x; v1 += o.y;
                        *(float2*)cp = make_float2(v0, v1);
                    }
                } else {
                    v0 = 0.0f; v1 = 0.0f;
                }
                if (OUTM >= 1) {
                    *(uint32_t*)(P + (size_t)m * KP + n) = pack_h2(v0, v1);
                }
            }
        }
    }
}

// ---------------------------------------------------------------------------
// CSR aggregation: 1 node per 160-thread block, pipelined edge loop.
// Writes fp16 plane directly.
// ---------------------------------------------------------------------------
__global__ __launch_bounds__(160)
void agg_kernel(const float* __restrict__ x, const float* __restrict__ tab,
                const int* __restrict__ ei, __half* __restrict__ P) {
    int c = blockIdx.x;
    int lane = threadIdx.x;
    if (lane >= HID / 4) return;
    int s = g_off[c], epd = g_off[c + 1];
    float4 acc = make_float4(0.f, 0.f, 0.f, 0.f);
    const float* xp = x + 4 * lane;
    const float* tp = tab + 4 * lane;
    int r = 0, i0 = 0; float f = 0.f;
    if (s < epd) {
        int e = g_csr[s];
        r = ei[e]; i0 = g_ei0[e]; f = g_efr[e];
    }
    for (int j = s; j < epd; j++) {
        float4 xv = *(const float4*)(xp + (size_t)r * HID);
        float4 w0 = *(const float4*)(tp + (size_t)i0 * HID);
        float4 w1 = *(const float4*)(tp + (size_t)(i0 + 1) * HID);
        int rn = r, i0n = i0; float fn = f;
        if (j + 1 < epd) {
            int en = g_csr[j + 1];
            rn = ei[en]; i0n = g_ei0[en]; fn = g_efr[en];
        }
        acc.x += xv.x * fmaf(f, w1.x - w0.x, w0.x);
        acc.y += xv.y * fmaf(f, w1.y - w0.y, w0.y);
        acc.z += xv.z * fmaf(f, w1.z - w0.z, w0.z);
        acc.w += xv.w * fmaf(f, w1.w - w0.w, w0.w);
        r = rn; i0 = i0n; f = fn;
    }
    float av[4] = {acc.x, acc.y, acc.z, acc.w};
    *(uint2*)(P + (size_t)c * KP + 4 * lane) = pack_h4(av);
}

// ---------------------------------------------------------------------------
// Launch
// ---------------------------------------------------------------------------
extern "C" void kernel_launch(void* const* d_in, const int* in_sizes, int n_in,
                              void* d_out, int out_size) {
    const int*   z      = (const int*)  d_in[0];
    const float* pos    = (const float*)d_in[1];
    const int*   ei     = (const int*)  d_in[2];
    const float* emb    = (const float*)d_in[3];
    const float* mlp1_w = (const float*)d_in[4];
    const float* mlp1_b = (const float*)d_in[5];
    const float* mlp2_w = (const float*)d_in[6];
    const float* mlp2_b = (const float*)d_in[7];
    const float* lin1_w = (const float*)d_in[8];
    const float* lin2_w = (const float*)d_in[9];
    const float* lin2_b = (const float*)d_in[10];
    const float* lin_w  = (const float*)d_in[11];
    const float* lin_b  = (const float*)d_in[12];
    float* h = (float*)d_out;

    cudaFuncSetAttribute((const void*)hgemm<1,1,0,1>, cudaFuncAttributeMaxDynamicSharedMemorySize, SMEM_BYTES);
    cudaFuncSetAttribute((const void*)hgemm<1,0,1,0>, cudaFuncAttributeMaxDynamicSharedMemorySize, SMEM_BYTES);
    cudaFuncSetAttribute((const void*)hgemm<0,0,0,0>, cudaFuncAttributeMaxDynamicSharedMemorySize, SMEM_BYTES);
    cudaFuncSetAttribute((const void*)hgemm<1,0,0,2>, cudaFuncAttributeMaxDynamicSharedMemorySize, SMEM_BYTES);

    __half *ea, *t1, *hh, *ag, *x2, *em, *w1, *wb;
    float *tab, *x, *xe, *Ct;
    int *cnt;
    cudaGetSymbolAddress((void**)&ea, g_ea);   cudaGetSymbolAddress((void**)&t1, g_T1);
    cudaGetSymbolAddress((void**)&hh, g_h);    cudaGetSymbolAddress((void**)&ag, g_ag);
    cudaGetSymbolAddress((void**)&x2, g_x2);   cudaGetSymbolAddress((void**)&em, g_em);
    cudaGetSymbolAddress((void**)&w1, g_w1);   cudaGetSymbolAddress((void**)&wb, g_wb);
    cudaGetSymbolAddress((void**)&tab, g_tab); cudaGetSymbolAddress((void**)&x,  g_x);
    cudaGetSymbolAddress((void**)&xe, g_xe);   cudaGetSymbolAddress((void**)&Ct, g_Ct);
    cudaGetSymbolAddress((void**)&cnt, g_cnt);

    // Prologue
    cudaMemsetAsync(cnt, 0, NN * sizeof(int));
    {
        dim3 gW((600 * KP / 4 + 255) / 256, 1, NITR * 4);
        cvt_wb_kernel<<<gW, 256>>>(mlp2_w, lin1_w, lin2_w, lin_w);
        dim3 gW1((600 * KP1 + 255) / 256, 1, NITR);
        cvt_w1_kernel<<<gW1, 256>>>(mlp1_w);
    }
    prologue_kernel<<<B_TAB + B_EDGE + B_EMB + B_INIT, 256>>>(z, emb, pos, ei, h);
    // Table GEMMs (ncu -s 5 -c 1 samples #6 = the K=608 hgemm)
    {
        dim3 gT(5, GT / 128, NITR);   // 240 blocks
        hgemm<1,1,0,1><<<gT, 256, SMEM_BYTES>>>(ea, w1,
            mlp1_b, nullptr, nullptr, t1, GT, KP1, KP1,
            0, (size_t)640 * KP1, HID, 0, (size_t)GT * KP);
        hgemm<1,0,1,0><<<gT, 256, SMEM_BYTES>>>(t1, wb,
            mlp2_b, Ct, tab, nullptr, GT, KC, KP,
            (size_t)GT * KP, (size_t)4 * 640 * KP, HID, (size_t)GT * HID, 0);
    }
    // Iteration-0 x via embedding table
    {
        __half* l1w0 = wb + (size_t)1 * 640 * KP;   // it=0, wix=1
        dim3 gZ(5, 1, 1);
        hgemm<0,0,0,0><<<gZ, 256, SMEM_BYTES>>>(em, l1w0,
            nullptr, nullptr, xe, nullptr, NZ, KC, KP, 0, 0, 0, 0, 0);
        xgather_kernel<<<(int)(((long)NN * HID / 4 + 255) / 256), 256>>>(z, xe, x);
    }
    // CSR finalize
    csr_scan_kernel<<<1, 1024>>>();
    csr_place_kernel<<<(NE + 127) / 128, 128>>>(ei);

    dim3 gN(5, NPAD / 128, 1);   // 5 x 79 = 395 tiles

    for (int it = 0; it < NITR; it++) {
        const float* l2b = lin2_b + (size_t)it * HID;
        const float* lb  = lin_b  + (size_t)it * HID;
        __half* l1w = wb + ((size_t)it * 4 + 1) * 640 * KP;
        __half* l2w = wb + ((size_t)it * 4 + 2) * 640 * KP;
        __half* lw  = wb + ((size_t)it * 4 + 3) * 640 * KP;

        if (it > 0) {
            // x = h @ l1w^T -> fp32
            hgemm<0,0,0,0><<<gN, 256, SMEM_BYTES>>>(hh, l1w,
                nullptr, nullptr, x, nullptr, NN, KC, KP, 0, 0, 0, 0, 0);
        }
        // agg plane = CSR segment sum of x[row]*lerp(tab[it])
        agg_kernel<<<NN, 160>>>(x, tab + (size_t)it * GT * HID, ei, ag);
        // x2 = ssp(agg @ l2w^T + l2b) -> plane
        hgemm<1,1,0,1><<<gN, 256, SMEM_BYTES>>>(ag, l2w,
            l2b, nullptr, nullptr, x2, NN, KC, KP, 0, 0, 0, 0, 0);
        // h += x2 @ lw^T + lb ; refresh h plane
        hgemm<1,0,0,2><<<gN, 256, SMEM_BYTES>>>(x2, lw,
            lb, nullptr, h, hh, NN, KC, KP, 0, 0, 0, 0, 0);
    }
}

// round 13
// speedup vs baseline: 1.9465x; 1.0380x over previous
#include <cuda_runtime.h>
#include <cuda_bf16.h>
#include <cuda_fp16.h>
#include <math.h>
#include <stdint.h>

// Problem constants
#define NN   10000
#define NE   100000
#define HID  600
#define NGS  50
#define NITR 6
#define NZ   100        // embedding table rows

#define KP   640        // plane row stride (elements)
#define KC   608        // K compute extent (19 chunks of 32)
#define KP1  64         // padded gaussian K
#define NPAD 10112      // 79*128
#define GT   1024       // filter table resolution
#define DMAX 13.86f
#define STG  16384      // stage = A(8KB) + B(8KB)
#define SMEM_BYTES (4 * STG)   // 4-stage pipeline, 64KB

// ---------------------------------------------------------------------------
// Scratch (__device__ globals; zero-initialized)
// ---------------------------------------------------------------------------
__device__ __align__(256) __half g_ea [(size_t)GT * KP1];
__device__ __align__(256) __half g_T1 [(size_t)NITR * GT * KP];
__device__ __align__(256) __half g_h  [(size_t)NPAD * KP];
__device__ __align__(256) __half g_ag [(size_t)NPAD * KP];
__device__ __align__(256) __half g_x2 [(size_t)NPAD * KP];
__device__ __align__(256) __half g_xh [(size_t)NPAD * KP];   // x plane (fp16)
__device__ __align__(256) __half g_em [(size_t)128 * KP];
__device__ __align__(256) __half g_w1 [(size_t)NITR * 640 * KP1];
__device__ __align__(256) __half g_wb [(size_t)NITR * 4 * 640 * KP];
__device__ __align__(256) __half g_tab[(size_t)NITR * GT * HID];  // fp16 tables
__device__ float g_xe  [(size_t)NZ * HID];
__device__ float g_Ct  [GT];
__device__ int   g_ei0 [NE];
__device__ float g_efr [NE];
__device__ int   g_cnt [NN];
__device__ int   g_off [NN + 1];
__device__ int   g_rank[NE];
__device__ int   g_csr [NE];

// ---------------------------------------------------------------------------
// Helpers
// ---------------------------------------------------------------------------
__device__ __forceinline__ uint32_t smem_u32(const void* p) {
    uint32_t a;
    asm("{ .reg .u64 t; cvta.to.shared.u64 t, %1; cvt.u32.u64 %0, t; }" : "=r"(a) : "l"(p));
    return a;
}
__device__ __forceinline__ void ldsm4(uint32_t (&r)[4], uint32_t addr) {
    asm volatile("ldmatrix.sync.aligned.m8n8.x4.shared.b16 {%0,%1,%2,%3}, [%4];"
                 : "=r"(r[0]), "=r"(r[1]), "=r"(r[2]), "=r"(r[3]) : "r"(addr));
}
__device__ __forceinline__ void mma16816h(float (&d)[4], const uint32_t (&a)[4],
                                          uint32_t b0, uint32_t b1) {
    asm volatile("mma.sync.aligned.m16n8k16.row.col.f32.f16.f16.f32 "
                 "{%0,%1,%2,%3}, {%4,%5,%6,%7}, {%8,%9}, {%0,%1,%2,%3};"
                 : "+f"(d[0]), "+f"(d[1]), "+f"(d[2]), "+f"(d[3])
                 : "r"(a[0]), "r"(a[1]), "r"(a[2]), "r"(a[3]), "r"(b0), "r"(b1));
}
__device__ __forceinline__ void cpa16(uint32_t dst, const void* src) {
    asm volatile("cp.async.cg.shared.global [%0], [%1], 16;" :: "r"(dst), "l"(src));
}
__device__ __forceinline__ float ssp_f(float v) {
    float av = fabsf(v);
    return fmaxf(v, 0.0f) + log1pf(expf(-av)) - 0.69314718055994530942f;
}
__device__ __forceinline__ uint32_t pack_h2(float a, float b) {
    __half2 p = __floats2half2_rn(a, b);
    return *(uint32_t*)&p;
}
__device__ __forceinline__ uint2 pack_h4(const float* v) {
    uint2 u;
    u.x = pack_h2(v[0], v[1]);
    u.y = pack_h2(v[2], v[3]);
    return u;
}
__device__ __forceinline__ float4 h4_to_f4(uint2 u) {
    float2 a = __half22float2(*(__half2*)&u.x);
    float2 b = __half22float2(*(__half2*)&u.y);
    return make_float4(a.x, a.y, b.x, b.y);
}

// ---------------------------------------------------------------------------
// Fused prologue: (a) table geometry, (b) edge prep, (c) emb conv, (d) h init
// ---------------------------------------------------------------------------
#define B_TAB  (GT / 256)                        // 4
#define B_EDGE ((NE + 255) / 256)                // 391
#define B_EMB  ((128 * KP) / 1024)               // 80
#define B_INIT ((NN * KP) / 1024)                // 6250

__global__ void prologue_kernel(const int* __restrict__ z, const float* __restrict__ emb,
                                const float* __restrict__ pos, const int* __restrict__ ei,
                                float* __restrict__ hout) {
    int bx = blockIdx.x;
    if (bx < B_TAB) {
        int g = bx * 256 + threadIdx.x;
        float d = (float)g * (DMAX / (float)(GT - 1));
        g_Ct[g] = 0.5f * (cosf(d * (float)(M_PI / 10.0)) + 1.0f);
        const float step  = 10.0f / 49.0f;
        const float coeff = -0.5f / (step * step);
        __half* eh = g_ea + (size_t)g * KP1;
#pragma unroll 8
        for (int k = 0; k < KP1; k++) {
            float v = 0.0f;
            if (k < NGS) { float t = d - step * (float)k; v = expf(coeff * t * t); }
            eh[k] = __float2half_rn(v);
        }
    } else if (bx < B_TAB + B_EDGE) {
        int e = (bx - B_TAB) * 256 + threadIdx.x;
        if (e >= NE) return;
        int r = ei[e], c = ei[NE + e];
        float dx = pos[3*r+0] - pos[3*c+0];
        float dy = pos[3*r+1] - pos[3*c+1];
        float dz = pos[3*r+2] - pos[3*c+2];
        float d = sqrtf(dx*dx + dy*dy + dz*dz);
        float t = d * ((float)(GT - 1) / DMAX);
        int i0 = (int)t;
        if (i0 > GT - 2) i0 = GT - 2;
        g_ei0[e] = i0;
        g_efr[e] = t - (float)i0;
        g_rank[e] = atomicAdd(&g_cnt[c], 1);
    } else if (bx < B_TAB + B_EDGE + B_EMB) {
        long i = ((long)(bx - B_TAB - B_EDGE) * 256 + threadIdx.x) * 4;
        int r = (int)(i / KP), k = (int)(i - (long)r * KP);
        float v[4] = {0.f, 0.f, 0.f, 0.f};
        if (r < NZ && k < HID) *(float4*)v = *(const float4*)(emb + (size_t)r * HID + k);
        *(uint2*)(g_em + i) = pack_h4(v);
    } else {
        long i = ((long)(bx - B_TAB - B_EDGE - B_EMB) * 256 + threadIdx.x) * 4;
        int n = (int)(i / KP), k = (int)(i - (long)n * KP);
        float v[4] = {0.f, 0.f, 0.f, 0.f};
        if (k < HID) {
            *(float4*)v = *(const float4*)(emb + (size_t)z[n] * HID + k);
            *(float4*)(hout + (size_t)n * HID + k) = *(float4*)v;
        }
        *(uint2*)(g_h + i) = pack_h4(v);
    }
}

// Exclusive scan of g_cnt -> g_off (single block)
__global__ __launch_bounds__(1024)
void csr_scan_kernel() {
    __shared__ int part[1024];
    int t = threadIdx.x;
    int base = t * 10;
    int loc[10];
    int s = 0;
#pragma unroll
    for (int i = 0; i < 10; i++) {
        int idx = base + i;
        loc[i] = s;
        s += (idx < NN) ? g_cnt[idx] : 0;
    }
    part[t] = s;
    __syncthreads();
    for (int off = 1; off < 1024; off <<= 1) {
        int v = (t >= off) ? part[t - off] : 0;
        __syncthreads();
        if (t >= off) part[t] += v;
        __syncthreads();
    }
    int pre = (t > 0) ? part[t - 1] : 0;
#pragma unroll
    for (int i = 0; i < 10; i++) {
        int idx = base + i;
        if (idx < NN) g_off[idx] = pre + loc[i];
    }
    if (t == 1023) g_off[NN] = part[1023];
}

__global__ void csr_place_kernel(const int* __restrict__ ei) {
    int e = blockIdx.x * blockDim.x + threadIdx.x;
    if (e >= NE) return;
    int c = ei[NE + e];
    g_csr[g_off[c] + g_rank[e]] = e;
}

// Batched 4-wide convert of 24 HID x HID weights (z = it*4 + wix)
__global__ void cvt_wb_kernel(const float* __restrict__ w2, const float* __restrict__ l1,
                              const float* __restrict__ l2, const float* __restrict__ lw) {
    int zz = blockIdx.z;
    int wix = zz & 3, it = zz >> 2;
    const float* src = ((wix == 0) ? w2 : (wix == 1) ? l1 : (wix == 2) ? l2 : lw)
                       + (size_t)it * HID * HID;
    __half* dh = g_wb + (size_t)zz * 640 * KP;
    long i = ((long)blockIdx.x * blockDim.x + threadIdx.x) * 4;
    if (i >= (long)600 * KP) return;
    int r = (int)(i / KP), k = (int)(i - (long)r * KP);
    float v[4] = {0.f, 0.f, 0.f, 0.f};
    if (k < HID) *(float4*)v = *(const float4*)(src + (size_t)r * HID + k);
    *(uint2*)(dh + i) = pack_h4(v);
}

// Batched convert of 6 mlp1 weights (z = it)
__global__ void cvt_w1_kernel(const float* __restrict__ w1) {
    int it = blockIdx.z;
    const float* src = w1 + (size_t)it * HID * NGS;
    __half* dh = g_w1 + (size_t)it * 640 * KP1;
    long i = blockIdx.x * (long)blockDim.x + threadIdx.x;
    if (i >= (long)600 * KP1) return;
    int r = (int)(i / KP1), k = (int)(i - (long)r * KP1);
    float v = (k < NGS) ? src[(size_t)r * NGS + k] : 0.0f;
    dh[i] = __float2half_rn(v);
}

// x plane[n] = fp16(xe[z[n]])  (iteration-0 x)
__global__ void xgather_kernel(const int* __restrict__ z, const float* __restrict__ xe,
                               __half* __restrict__ xh) {
    long i = ((long)blockIdx.x * blockDim.x + threadIdx.x) * 4;
    if (i >= (long)NN * HID) return;
    int n = (int)(i / HID), k = (int)(i - (long)n * HID);
    float v[4];
    *(float4*)v = *(const float4*)(xe + (size_t)z[n] * HID + k);
    *(uint2*)(xh + (size_t)n * KP + k) = pack_h4(v);
}

// ---------------------------------------------------------------------------
// fp16 HMMA GEMM, 128x128 tile, 2 CTAs/SM, 4-stage cp.async pipeline
// out[m,n] = sum_k A[m,k]*B[n,k]
// OUTM: 0 fp32 Cf; 1 fp16 plane (stride pLd, zero-pads); 2 fp32 residual + plane;
//       3 fp16 valid-only (stride pLd) — for the filter table
// ---------------------------------------------------------------------------
template <int DO_BIAS, int DO_SSP, int DO_RSCALE, int OUTM>
__global__ __launch_bounds__(256, 2)
void hgemm(const __half* __restrict__ A, const __half* __restrict__ B,
           const float* __restrict__ bias, const float* __restrict__ rowscale,
           float* __restrict__ Cf, __half* __restrict__ P,
           int M, int Kc, int ldA, int pLd,
           size_t aZ, size_t bZ, size_t biasZ, size_t cZ, size_t pZ) {
    extern __shared__ char smem[];
    const uint32_t sb = smem_u32(smem);
    const int tid = threadIdx.x, lane = tid & 31, wid = tid >> 5;
    const int wm = wid >> 2, wn = wid & 3;
    const int m0 = blockIdx.y * 128, n0 = blockIdx.x * 128;
    const int zz = blockIdx.z;

    A += (size_t)zz * aZ;
    B += (size_t)zz * bZ;
    if (DO_BIAS)   bias += (size_t)zz * biasZ;
    if (OUTM == 0 || OUTM == 2) Cf += (size_t)zz * cZ;
    if (OUTM >= 1) P += (size_t)zz * pZ;

    float acc[4][4][4];
#pragma unroll
    for (int a = 0; a < 4; a++)
#pragma unroll
        for (int b = 0; b < 4; b++)
#pragma unroll
            for (int c = 0; c < 4; c++) acc[a][b][c] = 0.0f;

    const int lr = tid >> 2;
    const int lc = tid & 3;

#define PREFETCH(chunk, stg) do {                                              \
        uint32_t sbase = sb + (stg) * STG;                                     \
        int k0 = (chunk) * 32;                                                 \
        _Pragma("unroll")                                                      \
        for (int i = 0; i < 2; i++) {                                          \
            int r = i * 64 + lr;                                               \
            uint32_t sw = (uint32_t)((lc ^ ((r >> 1) & 3)) * 16);              \
            cpa16(sbase + r * 64 + sw,                                         \
                  A + (size_t)(m0 + r) * ldA + k0 + lc * 8);                   \
            cpa16(sbase + 8192 + r * 64 + sw,                                  \
                  B + (size_t)(n0 + r) * ldA + k0 + lc * 8);                   \
        }                                                                      \
        asm volatile("cp.async.commit_group;" ::: "memory");                   \
    } while (0)

    const int nc = Kc >> 5;
    PREFETCH(0, 0);
    if (nc > 1) PREFETCH(1, 1);
    if (nc > 2) PREFETCH(2, 2);
    for (int ch = 0; ch < nc; ch++) {
        int stg = ch & 3;
        if (ch + 2 < nc) {
            asm volatile("cp.async.wait_group 2;" ::: "memory");
        } else if (ch + 1 < nc) {
            asm volatile("cp.async.wait_group 1;" ::: "memory");
        } else {
            asm volatile("cp.async.wait_group 0;" ::: "memory");
        }
        __syncthreads();
        if (ch + 3 < nc) PREFETCH(ch + 3, (ch + 3) & 3);

        uint32_t Abase = sb + stg * STG;
        uint32_t Bbase = Abase + 8192;
#pragma unroll
        for (int ks = 0; ks < 2; ks++) {
            int arow = wm * 64 + (lane & 15);
            int brow = wn * 32 + (lane & 15);
            int cch  = ks * 2 + (lane >> 4);
            uint32_t af[4][4], bf[2][4];
#pragma unroll
            for (int p = 0; p < 2; p++) {
                int r = brow + p * 16;
                ldsm4(bf[p], Bbase + r * 64 + ((cch ^ ((r >> 1) & 3)) * 16));
            }
#pragma unroll
            for (int mi = 0; mi < 4; mi++) {
                int r = arow + mi * 16;
                ldsm4(af[mi], Abase + r * 64 + ((cch ^ ((r >> 1) & 3)) * 16));
            }
#pragma unroll
            for (int mi = 0; mi < 4; mi++)
#pragma unroll
                for (int ni = 0; ni < 4; ni++)
                    mma16816h(acc[mi][ni], af[mi], bf[ni >> 1][ni & 1], bf[ni >> 1][(ni & 1) + 2]);
        }
        __syncthreads();
    }
#undef PREFETCH

    const int gid = lane >> 2, tg = lane & 3;
#pragma unroll
    for (int mi = 0; mi < 4; mi++) {
#pragma unroll
        for (int ni = 0; ni < 4; ni++) {
            int n = n0 + wn * 32 + ni * 8 + tg * 2;
            bool nok = (n < HID);
#pragma unroll
            for (int half = 0; half < 2; half++) {
                int m = m0 + wm * 64 + mi * 16 + gid + half * 8;
                float v0 = acc[mi][ni][half * 2 + 0];
                float v1 = acc[mi][ni][half * 2 + 1];
                bool mok = (m < M);
                if (mok && nok) {
                    if (DO_BIAS) { v0 += bias[n]; v1 += bias[n + 1]; }
                    if (DO_SSP)  { v0 = ssp_f(v0); v1 = ssp_f(v1); }
                    if (DO_RSCALE) { float rs = rowscale[m]; v0 *= rs; v1 *= rs; }
                    if (OUTM == 0) {
                        *(float2*)(Cf + (size_t)m * HID + n) = make_float2(v0, v1);
                    } else if (OUTM == 2) {
                        float* cp = Cf + (size_t)m * HID + n;
                        float2 o = *(float2*)cp;
                        v0 += o.x; v1 += o.y;
                        *(float2*)cp = make_float2(v0, v1);
                    }
                    if (OUTM == 3) {
                        *(uint32_t*)(P + (size_t)m * pLd + n) = pack_h2(v0, v1);
                    }
                } else {
                    v0 = 0.0f; v1 = 0.0f;
                }
                if (OUTM == 1 || OUTM == 2) {
                    *(uint32_t*)(P + (size_t)m * pLd + n) = pack_h2(v0, v1);
                }
            }
        }
    }
}

// ---------------------------------------------------------------------------
// CSR aggregation: 1 node per 160-thread block, all-fp16 operands.
// acc(fp32) = sum_e x16[row_e]*lerp(tab16); writes fp16 plane.
// ---------------------------------------------------------------------------
__global__ __launch_bounds__(160)
void agg_kernel(const __half* __restrict__ xh, const __half* __restrict__ tab,
                const int* __restrict__ ei, __half* __restrict__ P) {
    int c = blockIdx.x;
    int lane = threadIdx.x;
    if (lane >= HID / 4) return;
    int s = g_off[c], epd = g_off[c + 1];
    float4 acc = make_float4(0.f, 0.f, 0.f, 0.f);
    const __half* xp = xh + 4 * lane;
    const __half* tp = tab + 4 * lane;
    int r = 0, i0 = 0; float f = 0.f;
    if (s < epd) {
        int e = g_csr[s];
        r = ei[e]; i0 = g_ei0[e]; f = g_efr[e];
    }
    for (int j = s; j < epd; j++) {
        uint2 xu = *(const uint2*)(xp + (size_t)r * KP);
        uint2 w0u = *(const uint2*)(tp + (size_t)i0 * HID);
        uint2 w1u = *(const uint2*)(tp + (size_t)(i0 + 1) * HID);
        int rn = r, i0n = i0; float fn = f;
        if (j + 1 < epd) {
            int en = g_csr[j + 1];
            rn = ei[en]; i0n = g_ei0[en]; fn = g_efr[en];
        }
        float4 xv = h4_to_f4(xu);
        float4 w0 = h4_to_f4(w0u);
        float4 w1 = h4_to_f4(w1u);
        acc.x += xv.x * fmaf(f, w1.x - w0.x, w0.x);
        acc.y += xv.y * fmaf(f, w1.y - w0.y, w0.y);
        acc.z += xv.z * fmaf(f, w1.z - w0.z, w0.z);
        acc.w += xv.w * fmaf(f, w1.w - w0.w, w0.w);
        r = rn; i0 = i0n; f = fn;
    }
    float av[4] = {acc.x, acc.y, acc.z, acc.w};
    *(uint2*)(P + (size_t)c * KP + 4 * lane) = pack_h4(av);
}

// ---------------------------------------------------------------------------
// Launch
// ---------------------------------------------------------------------------
extern "C" void kernel_launch(void* const* d_in, const int* in_sizes, int n_in,
                              void* d_out, int out_size) {
    const int*   z      = (const int*)  d_in[0];
    const float* pos    = (const float*)d_in[1];
    const int*   ei     = (const int*)  d_in[2];
    const float* emb    = (const float*)d_in[3];
    const float* mlp1_w = (const float*)d_in[4];
    const float* mlp1_b = (const float*)d_in[5];
    const float* mlp2_w = (const float*)d_in[6];
    const float* mlp2_b = (const float*)d_in[7];
    const float* lin1_w = (const float*)d_in[8];
    const float* lin2_w = (const float*)d_in[9];
    const float* lin2_b = (const float*)d_in[10];
    const float* lin_w  = (const float*)d_in[11];
    const float* lin_b  = (const float*)d_in[12];
    float* h = (float*)d_out;

    cudaFuncSetAttribute((const void*)hgemm<1,1,0,1>, cudaFuncAttributeMaxDynamicSharedMemorySize, SMEM_BYTES);
    cudaFuncSetAttribute((const void*)hgemm<1,0,1,3>, cudaFuncAttributeMaxDynamicSharedMemorySize, SMEM_BYTES);
    cudaFuncSetAttribute((const void*)hgemm<0,0,0,0>, cudaFuncAttributeMaxDynamicSharedMemorySize, SMEM_BYTES);
    cudaFuncSetAttribute((const void*)hgemm<0,0,0,1>, cudaFuncAttributeMaxDynamicSharedMemorySize, SMEM_BYTES);
    cudaFuncSetAttribute((const void*)hgemm<1,0,0,2>, cudaFuncAttributeMaxDynamicSharedMemorySize, SMEM_BYTES);

    __half *ea, *t1, *hh, *ag, *x2, *xh, *em, *w1, *wb, *tab;
    float *xe, *Ct;
    int *cnt;
    cudaGetSymbolAddress((void**)&ea, g_ea);   cudaGetSymbolAddress((void**)&t1, g_T1);
    cudaGetSymbolAddress((void**)&hh, g_h);    cudaGetSymbolAddress((void**)&ag, g_ag);
    cudaGetSymbolAddress((void**)&x2, g_x2);   cudaGetSymbolAddress((void**)&xh, g_xh);
    cudaGetSymbolAddress((void**)&em, g_em);   cudaGetSymbolAddress((void**)&w1, g_w1);
    cudaGetSymbolAddress((void**)&wb, g_wb);   cudaGetSymbolAddress((void**)&tab, g_tab);
    cudaGetSymbolAddress((void**)&xe, g_xe);   cudaGetSymbolAddress((void**)&Ct, g_Ct);
    cudaGetSymbolAddress((void**)&cnt, g_cnt);

    // Prologue
    cudaMemsetAsync(cnt, 0, NN * sizeof(int));
    {
        dim3 gW((600 * KP / 4 + 255) / 256, 1, NITR * 4);
        cvt_wb_kernel<<<gW, 256>>>(mlp2_w, lin1_w, lin2_w, lin_w);
        dim3 gW1((600 * KP1 + 255) / 256, 1, NITR);
        cvt_w1_kernel<<<gW1, 256>>>(mlp1_w);
    }
    prologue_kernel<<<B_TAB + B_EDGE + B_EMB + B_INIT, 256>>>(z, emb, pos, ei, h);
    // Table GEMMs
    {
        dim3 gT(5, GT / 128, NITR);   // 240 blocks
        hgemm<1,1,0,1><<<gT, 256, SMEM_BYTES>>>(ea, w1,
            mlp1_b, nullptr, nullptr, t1, GT, KP1, KP1, KP,
            0, (size_t)640 * KP1, HID, 0, (size_t)GT * KP);
        // tab (fp16, HID stride) = (T1 @ w2^T + b2) * Ct
        hgemm<1,0,1,3><<<gT, 256, SMEM_BYTES>>>(t1, wb,
            mlp2_b, Ct, nullptr, tab, GT, KC, KP, HID,
            (size_t)GT * KP, (size_t)4 * 640 * KP, HID, 0, (size_t)GT * HID);
    }
    // Iteration-0 x via embedding table: xe = emb @ l1w0^T (fp32), then gather->fp16
    {
        __half* l1w0 = wb + (size_t)1 * 640 * KP;   // it=0, wix=1
        dim3 gZ(5, 1, 1);
        hgemm<0,0,0,0><<<gZ, 256, SMEM_BYTES>>>(em, l1w0,
            nullptr, nullptr, xe, nullptr, NZ, KC, KP, 0, 0, 0, 0, 0, 0);
        xgather_kernel<<<(int)(((long)NN * HID / 4 + 255) / 256), 256>>>(z, xe, xh);
    }
    // CSR finalize
    csr_scan_kernel<<<1, 1024>>>();
    csr_place_kernel<<<(NE + 127) / 128, 128>>>(ei);

    dim3 gN(5, NPAD / 128, 1);   // 5 x 79 = 395 tiles

    for (int it = 0; it < NITR; it++) {
        const float* l2b = lin2_b + (size_t)it * HID;
        const float* lb  = lin_b  + (size_t)it * HID;
        __half* l1w = wb + ((size_t)it * 4 + 1) * 640 * KP;
        __half* l2w = wb + ((size_t)it * 4 + 2) * 640 * KP;
        __half* lw  = wb + ((size_t)it * 4 + 3) * 640 * KP;

        if (it > 0) {
            // x plane (fp16) = h @ l1w^T
            hgemm<0,0,0,1><<<gN, 256, SMEM_BYTES>>>(hh, l1w,
                nullptr, nullptr, nullptr, xh, NN, KC, KP, KP, 0, 0, 0, 0, 0);
        }
        // agg plane = CSR segment sum of x16[row]*lerp(tab16[it])
        agg_kernel<<<NN, 160>>>(xh, tab + (size_t)it * GT * HID, ei, ag);
        // x2 = ssp(agg @ l2w^T + l2b) -> plane
        hgemm<1,1,0,1><<<gN, 256, SMEM_BYTES>>>(ag, l2w,
            l2b, nullptr, nullptr, x2, NN, KC, KP, KP, 0, 0, 0, 0, 0);
        // h += x2 @ lw^T + lb ; refresh h plane
        hgemm<1,0,0,2><<<gN, 256, SMEM_BYTES>>>(x2, lw,
            lb, nullptr, h, hh, NN, KC, KP, KP, 0, 0, 0, 0, 0);
    }
}